// round 1
// baseline (speedup 1.0000x reference)
#include <cuda_runtime.h>
#include <cuda_bf16.h>

#define NSRC0 100000
#define NDST0 20000
#define NDST1 5000
#define NE0   160000
#define NE1   40000
#define IN_F  512
#define H_F   1024
#define N_CLS 256

// Scratch (device globals: allocation-free per harness rules)
__device__ float g_agg1[(long long)NDST0 * IN_F];   // 41 MB
__device__ float g_deg1[NDST0];
__device__ float g_h[(long long)NDST0 * H_F];       // 82 MB
__device__ float g_agg2[(long long)NDST1 * H_F];    // 20.5 MB
__device__ float g_deg2[NDST1];

// ---------------------------------------------------------------------------
// Zero accumulators + degree counters
// ---------------------------------------------------------------------------
__global__ void zero_all_kernel() {
    long long i = (long long)blockIdx.x * blockDim.x + threadIdx.x;
    if (i < (long long)NDST0 * IN_F) g_agg1[i] = 0.0f;
    if (i < (long long)NDST1 * H_F)  g_agg2[i] = 0.0f;
    if (i < NDST0) g_deg1[i] = 0.0f;
    if (i < NDST1) g_deg2[i] = 0.0f;
}

// ---------------------------------------------------------------------------
// Edge scatter-add: agg[dst] += feat[src]; deg[dst] += 1
// One thread per (edge, 4-float chunk)
// ---------------------------------------------------------------------------
__global__ void scatter_add_kernel(const float* __restrict__ feat,
                                   const int* __restrict__ esrc,
                                   const int* __restrict__ edst,
                                   float* __restrict__ agg,
                                   float* __restrict__ deg,
                                   int E, int F) {
    int idx = blockIdx.x * blockDim.x + threadIdx.x;
    int c4 = F >> 2;
    int e = idx / c4;
    if (e >= E) return;
    int c = idx - e * c4;
    int src = esrc[e];
    int dst = edst[e];
    float4 v = reinterpret_cast<const float4*>(feat)[(long long)src * c4 + c];
    float* a = agg + (long long)dst * F + (c << 2);
    atomicAdd(a + 0, v.x);
    atomicAdd(a + 1, v.y);
    atomicAdd(a + 2, v.z);
    atomicAdd(a + 3, v.w);
    if (c == 0) atomicAdd(deg + dst, 1.0f);
}

// ---------------------------------------------------------------------------
// Normalize: agg[r, :] /= max(deg[r], 1)
// ---------------------------------------------------------------------------
__global__ void normalize_kernel(float* __restrict__ agg,
                                 const float* __restrict__ deg,
                                 int rows, int F) {
    int idx = blockIdx.x * blockDim.x + threadIdx.x;
    int c4 = F >> 2;
    int r = idx / c4;
    if (r >= rows) return;
    int c = idx - r * c4;
    float s = 1.0f / fmaxf(deg[r], 1.0f);
    float4* p = reinterpret_cast<float4*>(agg) + (long long)r * c4 + c;
    float4 v = *p;
    v.x *= s; v.y *= s; v.z *= s; v.w *= s;
    *p = v;
}

// ---------------------------------------------------------------------------
// Dual-pair SGEMM with fused bias (+ optional ReLU):
//   C[M,N] = act( A0[M,K] @ B0[K,N] + A1[M,K] @ B1[K,N] + bias[N] )
// All row-major, lda = K, ldb = N. N % 128 == 0, K % 8 == 0. M arbitrary.
// 128x128 tile, BK=8, 256 threads, 8x8 per thread.
// ---------------------------------------------------------------------------
__global__ void __launch_bounds__(256)
sage_gemm_kernel(const float* __restrict__ A0, const float* __restrict__ A1,
                 const float* __restrict__ B0, const float* __restrict__ B1,
                 const float* __restrict__ bias, float* __restrict__ C,
                 int M, int N, int K, int doRelu) {
    const int BM = 128, BN = 128, BK = 8, TM = 8, TN = 8;
    __shared__ float As[BK][BM];
    __shared__ float Bs[BK][BN];

    int tid = threadIdx.x;
    int rowC = blockIdx.y * BM;
    int colC = blockIdx.x * BN;

    int tx = tid & 15;       // 0..15 -> N
    int ty = tid >> 4;       // 0..15 -> M

    // A-tile load: 128 rows x 8 cols = 1024 floats / 256 thr -> 1 float4 each
    int aRow = tid >> 1;           // 0..127
    int aCol = (tid & 1) << 2;     // 0 or 4
    // B-tile load: 8 rows x 128 cols -> 1 float4 each
    int bRow = tid >> 5;           // 0..7
    int bCol = (tid & 31) << 2;    // 0..124

    float acc[TM][TN];
#pragma unroll
    for (int i = 0; i < TM; i++)
#pragma unroll
        for (int j = 0; j < TN; j++) acc[i][j] = 0.0f;

    float regA[TM], regB[TN];

#pragma unroll 1
    for (int pass = 0; pass < 2; ++pass) {
        const float* A = pass ? A1 : A0;
        const float* B = pass ? B1 : B0;
#pragma unroll 1
        for (int k0 = 0; k0 < K; k0 += BK) {
            float4 av = make_float4(0.f, 0.f, 0.f, 0.f);
            int gr = rowC + aRow;
            if (gr < M)
                av = *reinterpret_cast<const float4*>(A + (long long)gr * K + k0 + aCol);
            As[aCol + 0][aRow] = av.x;
            As[aCol + 1][aRow] = av.y;
            As[aCol + 2][aRow] = av.z;
            As[aCol + 3][aRow] = av.w;

            float4 bv = *reinterpret_cast<const float4*>(
                B + (long long)(k0 + bRow) * N + colC + bCol);
            *reinterpret_cast<float4*>(&Bs[bRow][bCol]) = bv;

            __syncthreads();
#pragma unroll
            for (int kk = 0; kk < BK; ++kk) {
#pragma unroll
                for (int i = 0; i < TM; i++) regA[i] = As[kk][ty * TM + i];
#pragma unroll
                for (int j = 0; j < TN; j++) regB[j] = Bs[kk][tx * TN + j];
#pragma unroll
                for (int i = 0; i < TM; i++)
#pragma unroll
                    for (int j = 0; j < TN; j++)
                        acc[i][j] = fmaf(regA[i], regB[j], acc[i][j]);
            }
            __syncthreads();
        }
    }

    // Epilogue: bias (+ReLU), vectorized stores
#pragma unroll
    for (int i = 0; i < TM; i++) {
        int row = rowC + ty * TM + i;
        if (row >= M) continue;
#pragma unroll
        for (int j4 = 0; j4 < TN; j4 += 4) {
            int col = colC + tx * TN + j4;
            float4 v;
            v.x = acc[i][j4 + 0] + bias[col + 0];
            v.y = acc[i][j4 + 1] + bias[col + 1];
            v.z = acc[i][j4 + 2] + bias[col + 2];
            v.w = acc[i][j4 + 3] + bias[col + 3];
            if (doRelu) {
                v.x = fmaxf(v.x, 0.f); v.y = fmaxf(v.y, 0.f);
                v.z = fmaxf(v.z, 0.f); v.w = fmaxf(v.w, 0.f);
            }
            *reinterpret_cast<float4*>(C + (long long)row * N + col) = v;
        }
    }
}

// ---------------------------------------------------------------------------
extern "C" void kernel_launch(void* const* d_in, const int* in_sizes, int n_in,
                              void* d_out, int out_size) {
    const float* x        = (const float*)d_in[0];   // [100000,512]
    const float* W_self1  = (const float*)d_in[1];   // [512,1024]
    const float* W_neigh1 = (const float*)d_in[2];   // [512,1024]
    const float* b1       = (const float*)d_in[3];   // [1024]
    const float* W_self2  = (const float*)d_in[4];   // [1024,256]
    const float* W_neigh2 = (const float*)d_in[5];   // [1024,256]
    const float* b2       = (const float*)d_in[6];   // [256]
    const int*   e0_src   = (const int*)d_in[7];     // [160000]
    const int*   e0_dst   = (const int*)d_in[8];
    const int*   e1_src   = (const int*)d_in[9];     // [40000]
    const int*   e1_dst   = (const int*)d_in[10];
    float* out = (float*)d_out;                      // [5000,256]

    float *agg1, *deg1, *h, *agg2, *deg2;
    cudaGetSymbolAddress((void**)&agg1, g_agg1);
    cudaGetSymbolAddress((void**)&deg1, g_deg1);
    cudaGetSymbolAddress((void**)&h,    g_h);
    cudaGetSymbolAddress((void**)&agg2, g_agg2);
    cudaGetSymbolAddress((void**)&deg2, g_deg2);

    // 1. zero accumulators
    {
        long long mx = (long long)NDST0 * IN_F;  // largest array (10.24M)
        int blocks = (int)((mx + 255) / 256);
        zero_all_kernel<<<blocks, 256>>>();
    }

    // 2. layer-1 scatter mean numerator
    {
        long long total = (long long)NE0 * (IN_F / 4);
        scatter_add_kernel<<<(int)((total + 255) / 256), 256>>>(
            x, e0_src, e0_dst, agg1, deg1, NE0, IN_F);
    }
    // 3. normalize
    {
        long long total = (long long)NDST0 * (IN_F / 4);
        normalize_kernel<<<(int)((total + 255) / 256), 256>>>(agg1, deg1, NDST0, IN_F);
    }
    // 4. layer-1 fused dual-GEMM + bias + ReLU -> h [20000,1024]
    {
        dim3 grid(H_F / 128, (NDST0 + 127) / 128);
        sage_gemm_kernel<<<grid, 256>>>(x, agg1, W_self1, W_neigh1, b1, h,
                                        NDST0, H_F, IN_F, 1);
    }
    // 5. layer-2 scatter
    {
        long long total = (long long)NE1 * (H_F / 4);
        scatter_add_kernel<<<(int)((total + 255) / 256), 256>>>(
            h, e1_src, e1_dst, agg2, deg2, NE1, H_F);
    }
    // 6. normalize
    {
        long long total = (long long)NDST1 * (H_F / 4);
        normalize_kernel<<<(int)((total + 255) / 256), 256>>>(agg2, deg2, NDST1, H_F);
    }
    // 7. layer-2 fused dual-GEMM + bias -> out [5000,256]
    {
        dim3 grid(N_CLS / 128, (NDST1 + 127) / 128);
        sage_gemm_kernel<<<grid, 256>>>(h, agg2, W_self2, W_neigh2, b2, out,
                                        NDST1, N_CLS, H_F, 0);
    }
}

// round 4
// speedup vs baseline: 1.6943x; 1.6943x over previous
#include <cuda_runtime.h>
#include <cuda_bf16.h>
#include <cstdint>

#define NSRC0 100000
#define NDST0 20000
#define NDST1 5000
#define NE0   160000
#define NE1   40000
#define IN_F  512
#define H_F   1024
#define N_CLS 256

// ---------------------------------------------------------------------------
// Scratch (device globals: allocation-free per harness rules)
// ---------------------------------------------------------------------------
__device__ __align__(16) float g_agg1[(long long)NDST0 * IN_F];
__device__ float g_deg1[NDST0];
__device__ __align__(16) float g_h[(long long)NDST0 * H_F];
__device__ __align__(16) float g_agg2[(long long)NDST1 * H_F];
__device__ float g_deg2[NDST1];

// Pre-transposed, bf16-split weights: [N, K] layout (col-major B for row.col mma)
__device__ __align__(16) __nv_bfloat16 g_w1s_hi[H_F * IN_F];
__device__ __align__(16) __nv_bfloat16 g_w1s_lo[H_F * IN_F];
__device__ __align__(16) __nv_bfloat16 g_w1n_hi[H_F * IN_F];
__device__ __align__(16) __nv_bfloat16 g_w1n_lo[H_F * IN_F];
__device__ __align__(16) __nv_bfloat16 g_w2s_hi[N_CLS * H_F];
__device__ __align__(16) __nv_bfloat16 g_w2s_lo[N_CLS * H_F];
__device__ __align__(16) __nv_bfloat16 g_w2n_hi[N_CLS * H_F];
__device__ __align__(16) __nv_bfloat16 g_w2n_lo[N_CLS * H_F];

// ---------------------------------------------------------------------------
// Zero accumulators + degree counters
// ---------------------------------------------------------------------------
__global__ void zero_all_kernel() {
    long long i = (long long)blockIdx.x * blockDim.x + threadIdx.x;
    if (i < (long long)NDST0 * IN_F) g_agg1[i] = 0.0f;
    if (i < (long long)NDST1 * H_F)  g_agg2[i] = 0.0f;
    if (i < NDST0) g_deg1[i] = 0.0f;
    if (i < NDST1) g_deg2[i] = 0.0f;
}

// ---------------------------------------------------------------------------
// Transpose + bf16 hi/lo split: W[K,N] row-major -> hi/lo [N,K]
// ---------------------------------------------------------------------------
__global__ void transpose_split_kernel(const float* __restrict__ W,
                                       __nv_bfloat16* __restrict__ hi,
                                       __nv_bfloat16* __restrict__ lo,
                                       int K, int N) {
    __shared__ float t[32][33];
    int n0 = blockIdx.x * 32, k0 = blockIdx.y * 32;
    int tx = threadIdx.x, ty = threadIdx.y;
#pragma unroll
    for (int i = 0; i < 4; i++)
        t[ty + 8 * i][tx] = W[(long long)(k0 + ty + 8 * i) * N + n0 + tx];
    __syncthreads();
#pragma unroll
    for (int i = 0; i < 4; i++) {
        float v = t[tx][ty + 8 * i];
        __nv_bfloat16 h = __float2bfloat16(v);
        __nv_bfloat16 l = __float2bfloat16(v - __bfloat162float(h));
        long long o = (long long)(n0 + ty + 8 * i) * K + k0 + tx;
        hi[o] = h;
        lo[o] = l;
    }
}

// ---------------------------------------------------------------------------
// Edge scatter-add
// ---------------------------------------------------------------------------
__global__ void scatter_add_kernel(const float* __restrict__ feat,
                                   const int* __restrict__ esrc,
                                   const int* __restrict__ edst,
                                   float* __restrict__ agg,
                                   float* __restrict__ deg,
                                   int E, int F) {
    int idx = blockIdx.x * blockDim.x + threadIdx.x;
    int c4 = F >> 2;
    int e = idx / c4;
    if (e >= E) return;
    int c = idx - e * c4;
    int src = esrc[e];
    int dst = edst[e];
    float4 v = reinterpret_cast<const float4*>(feat)[(long long)src * c4 + c];
    float* a = agg + (long long)dst * F + (c << 2);
    atomicAdd(a + 0, v.x);
    atomicAdd(a + 1, v.y);
    atomicAdd(a + 2, v.z);
    atomicAdd(a + 3, v.w);
    if (c == 0) atomicAdd(deg + dst, 1.0f);
}

__global__ void normalize_kernel(float* __restrict__ agg,
                                 const float* __restrict__ deg,
                                 int rows, int F) {
    int idx = blockIdx.x * blockDim.x + threadIdx.x;
    int c4 = F >> 2;
    int r = idx / c4;
    if (r >= rows) return;
    int c = idx - r * c4;
    float s = 1.0f / fmaxf(deg[r], 1.0f);
    float4* p = reinterpret_cast<float4*>(agg) + (long long)r * c4 + c;
    float4 v = *p;
    v.x *= s; v.y *= s; v.z *= s; v.w *= s;
    *p = v;
}

// ---------------------------------------------------------------------------
// mma.sync helper: D(f32) += A(bf16,row) x B(bf16,col), m16n8k16
// ---------------------------------------------------------------------------
__device__ __forceinline__ void mma16816(float* c, uint32_t a0, uint32_t a1,
                                         uint32_t a2, uint32_t a3,
                                         uint32_t b0, uint32_t b1) {
    asm volatile(
        "mma.sync.aligned.m16n8k16.row.col.f32.bf16.bf16.f32 "
        "{%0,%1,%2,%3}, {%4,%5,%6,%7}, {%8,%9}, {%0,%1,%2,%3};"
        : "+f"(c[0]), "+f"(c[1]), "+f"(c[2]), "+f"(c[3])
        : "r"(a0), "r"(a1), "r"(a2), "r"(a3), "r"(b0), "r"(b1));
}

// ---------------------------------------------------------------------------
// Tensor-core dual-pair split-bf16 GEMM:
//   C = act( A0 @ B0^T + A1 @ B1^T + bias )
// A: [M,K] fp32 row-major.  B hi/lo: [N,K] bf16 (pre-transposed + split).
// C += Ahi*Bhi + Ahi*Blo + Alo*Bhi   (error ~2^-17)
// CTA tile 128x128, BK=32, 8 warps (4 M x 2 N), warp tile 32x64.
// APAD=40 elements (80-byte row stride): 16B-aligned rows for uint4 staging,
// and fragment loads hit 32 distinct banks (bank = (20g + t) mod 32).
// ---------------------------------------------------------------------------
#define APAD 40

__global__ void __launch_bounds__(256, 1)
sage_mma_gemm(const float* __restrict__ A0, const float* __restrict__ A1,
              const __nv_bfloat16* __restrict__ B0hi, const __nv_bfloat16* __restrict__ B0lo,
              const __nv_bfloat16* __restrict__ B1hi, const __nv_bfloat16* __restrict__ B1lo,
              const float* __restrict__ bias, float* __restrict__ C,
              int M, int N, int K, int doRelu) {
    __shared__ __align__(16) __nv_bfloat16 sAhi[128 * APAD];
    __shared__ __align__(16) __nv_bfloat16 sAlo[128 * APAD];
    __shared__ __align__(16) __nv_bfloat16 sBhi[128 * APAD];
    __shared__ __align__(16) __nv_bfloat16 sBlo[128 * APAD];

    int tid = threadIdx.x;
    int wid = tid >> 5;
    int lane = tid & 31;
    int g = lane >> 2;        // 0..7
    int t = lane & 3;         // 0..3
    int warpM = wid >> 1;     // 0..3
    int warpN = wid & 1;      // 0..1
    int rowC = blockIdx.y * 128;
    int colC = blockIdx.x * 128;

    float acc[2][8][4];
#pragma unroll
    for (int i = 0; i < 2; i++)
#pragma unroll
        for (int j = 0; j < 8; j++)
#pragma unroll
            for (int q = 0; q < 4; q++) acc[i][j][q] = 0.0f;

#pragma unroll 1
    for (int pass = 0; pass < 2; ++pass) {
        const float* A = pass ? A1 : A0;
        const __nv_bfloat16* Bhi = pass ? B1hi : B0hi;
        const __nv_bfloat16* Blo = pass ? B1lo : B0lo;
#pragma unroll 1
        for (int k0 = 0; k0 < K; k0 += 32) {
            // --- stage A chunk: 128 rows x 32 fp32 -> bf16 hi/lo (padded) ---
#pragma unroll
            for (int it = 0; it < 4; it++) {
                int linear = tid + it * 256;   // 0..1023 float4 slots
                int r = linear >> 3;           // 0..127
                int c4 = linear & 7;           // float4 within row
                float4 v = make_float4(0.f, 0.f, 0.f, 0.f);
                int gr = rowC + r;
                if (gr < M)
                    v = *reinterpret_cast<const float4*>(A + (long long)gr * K + k0 + (c4 << 2));
                __nv_bfloat16 h0 = __float2bfloat16(v.x);
                __nv_bfloat16 h1 = __float2bfloat16(v.y);
                __nv_bfloat16 h2 = __float2bfloat16(v.z);
                __nv_bfloat16 h3 = __float2bfloat16(v.w);
                __nv_bfloat16 l0 = __float2bfloat16(v.x - __bfloat162float(h0));
                __nv_bfloat16 l1 = __float2bfloat16(v.y - __bfloat162float(h1));
                __nv_bfloat16 l2 = __float2bfloat16(v.z - __bfloat162float(h2));
                __nv_bfloat16 l3 = __float2bfloat16(v.w - __bfloat162float(h3));
                uint32_t hi01 = ((uint32_t)__bfloat16_as_ushort(h1) << 16) | __bfloat16_as_ushort(h0);
                uint32_t hi23 = ((uint32_t)__bfloat16_as_ushort(h3) << 16) | __bfloat16_as_ushort(h2);
                uint32_t lo01 = ((uint32_t)__bfloat16_as_ushort(l1) << 16) | __bfloat16_as_ushort(l0);
                uint32_t lo23 = ((uint32_t)__bfloat16_as_ushort(l3) << 16) | __bfloat16_as_ushort(l2);
                int so = r * APAD + (c4 << 2);
                *reinterpret_cast<uint2*>(&sAhi[so]) = make_uint2(hi01, hi23);
                *reinterpret_cast<uint2*>(&sAlo[so]) = make_uint2(lo01, lo23);
            }
            // --- stage B chunk: 128 rows x 32 bf16 (hi + lo) ---
#pragma unroll
            for (int it = 0; it < 2; it++) {
                int linear = tid + it * 256;   // 0..511 16B slots
                int r = linear >> 2;           // 0..127
                int c = linear & 3;            // 16B unit in row
                long long go = (long long)(colC + r) * K + k0 + (c << 3);
                uint4 vh = *reinterpret_cast<const uint4*>(Bhi + go);
                uint4 vl = *reinterpret_cast<const uint4*>(Blo + go);
                int so = r * APAD + (c << 3);
                *reinterpret_cast<uint4*>(&sBhi[so]) = vh;
                *reinterpret_cast<uint4*>(&sBlo[so]) = vl;
            }
            __syncthreads();

            // --- 3 split terms x 2 k16-steps ---
#pragma unroll
            for (int s = 0; s < 3; s++) {
                const __nv_bfloat16* As = (s == 2) ? sAlo : sAhi;
                const __nv_bfloat16* Bs = (s == 1) ? sBlo : sBhi;
#pragma unroll
                for (int ks = 0; ks < 2; ks++) {
                    int kb = ks * 16 + 2 * t;
                    uint32_t a[2][4];
#pragma unroll
                    for (int i = 0; i < 2; i++) {
                        int r0 = warpM * 32 + i * 16 + g;
                        a[i][0] = *reinterpret_cast<const uint32_t*>(&As[r0 * APAD + kb]);
                        a[i][1] = *reinterpret_cast<const uint32_t*>(&As[(r0 + 8) * APAD + kb]);
                        a[i][2] = *reinterpret_cast<const uint32_t*>(&As[r0 * APAD + kb + 8]);
                        a[i][3] = *reinterpret_cast<const uint32_t*>(&As[(r0 + 8) * APAD + kb + 8]);
                    }
                    uint32_t b[8][2];
#pragma unroll
                    for (int j = 0; j < 8; j++) {
                        int n0 = warpN * 64 + j * 8 + g;
                        b[j][0] = *reinterpret_cast<const uint32_t*>(&Bs[n0 * APAD + kb]);
                        b[j][1] = *reinterpret_cast<const uint32_t*>(&Bs[n0 * APAD + kb + 8]);
                    }
#pragma unroll
                    for (int i = 0; i < 2; i++)
#pragma unroll
                        for (int j = 0; j < 8; j++)
                            mma16816(acc[i][j], a[i][0], a[i][1], a[i][2], a[i][3],
                                     b[j][0], b[j][1]);
                }
            }
            __syncthreads();
        }
    }

    // --- epilogue: bias (+ReLU), float2 stores ---
#pragma unroll
    for (int i = 0; i < 2; i++) {
#pragma unroll
        for (int j = 0; j < 8; j++) {
            int row = rowC + warpM * 32 + i * 16 + g;
            int col = colC + warpN * 64 + j * 8 + 2 * t;
            float bx = bias[col], by = bias[col + 1];
            float2 v0, v1;
            v0.x = acc[i][j][0] + bx; v0.y = acc[i][j][1] + by;
            v1.x = acc[i][j][2] + bx; v1.y = acc[i][j][3] + by;
            if (doRelu) {
                v0.x = fmaxf(v0.x, 0.f); v0.y = fmaxf(v0.y, 0.f);
                v1.x = fmaxf(v1.x, 0.f); v1.y = fmaxf(v1.y, 0.f);
            }
            if (row < M)
                *reinterpret_cast<float2*>(C + (long long)row * N + col) = v0;
            if (row + 8 < M)
                *reinterpret_cast<float2*>(C + (long long)(row + 8) * N + col) = v1;
        }
    }
}

// ---------------------------------------------------------------------------
extern "C" void kernel_launch(void* const* d_in, const int* in_sizes, int n_in,
                              void* d_out, int out_size) {
    const float* x        = (const float*)d_in[0];
    const float* W_self1  = (const float*)d_in[1];
    const float* W_neigh1 = (const float*)d_in[2];
    const float* b1       = (const float*)d_in[3];
    const float* W_self2  = (const float*)d_in[4];
    const float* W_neigh2 = (const float*)d_in[5];
    const float* b2       = (const float*)d_in[6];
    const int*   e0_src   = (const int*)d_in[7];
    const int*   e0_dst   = (const int*)d_in[8];
    const int*   e1_src   = (const int*)d_in[9];
    const int*   e1_dst   = (const int*)d_in[10];
    float* out = (float*)d_out;

    float *agg1, *deg1, *h, *agg2, *deg2;
    cudaGetSymbolAddress((void**)&agg1, g_agg1);
    cudaGetSymbolAddress((void**)&deg1, g_deg1);
    cudaGetSymbolAddress((void**)&h,    g_h);
    cudaGetSymbolAddress((void**)&agg2, g_agg2);
    cudaGetSymbolAddress((void**)&deg2, g_deg2);
    __nv_bfloat16 *w1s_hi, *w1s_lo, *w1n_hi, *w1n_lo, *w2s_hi, *w2s_lo, *w2n_hi, *w2n_lo;
    cudaGetSymbolAddress((void**)&w1s_hi, g_w1s_hi);
    cudaGetSymbolAddress((void**)&w1s_lo, g_w1s_lo);
    cudaGetSymbolAddress((void**)&w1n_hi, g_w1n_hi);
    cudaGetSymbolAddress((void**)&w1n_lo, g_w1n_lo);
    cudaGetSymbolAddress((void**)&w2s_hi, g_w2s_hi);
    cudaGetSymbolAddress((void**)&w2s_lo, g_w2s_lo);
    cudaGetSymbolAddress((void**)&w2n_hi, g_w2n_hi);
    cudaGetSymbolAddress((void**)&w2n_lo, g_w2n_lo);

    // 1. zero accumulators
    {
        long long mx = (long long)NDST0 * IN_F;
        zero_all_kernel<<<(int)((mx + 255) / 256), 256>>>();
    }
    // 2. weight transpose + bf16 split
    {
        dim3 b(32, 8);
        transpose_split_kernel<<<dim3(H_F / 32, IN_F / 32), b>>>(W_self1,  w1s_hi, w1s_lo, IN_F, H_F);
        transpose_split_kernel<<<dim3(H_F / 32, IN_F / 32), b>>>(W_neigh1, w1n_hi, w1n_lo, IN_F, H_F);
        transpose_split_kernel<<<dim3(N_CLS / 32, H_F / 32), b>>>(W_self2,  w2s_hi, w2s_lo, H_F, N_CLS);
        transpose_split_kernel<<<dim3(N_CLS / 32, H_F / 32), b>>>(W_neigh2, w2n_hi, w2n_lo, H_F, N_CLS);
    }
    // 3. layer-1 scatter + normalize
    {
        long long total = (long long)NE0 * (IN_F / 4);
        scatter_add_kernel<<<(int)((total + 255) / 256), 256>>>(
            x, e0_src, e0_dst, agg1, deg1, NE0, IN_F);
        total = (long long)NDST0 * (IN_F / 4);
        normalize_kernel<<<(int)((total + 255) / 256), 256>>>(agg1, deg1, NDST0, IN_F);
    }
    // 4. layer-1 dual-GEMM + bias + ReLU -> h [20000,1024]
    {
        dim3 grid(H_F / 128, (NDST0 + 127) / 128);
        sage_mma_gemm<<<grid, 256>>>(
            x, agg1, w1s_hi, w1s_lo, w1n_hi, w1n_lo, b1, h, NDST0, H_F, IN_F, 1);
    }
    // 5. layer-2 scatter + normalize
    {
        long long total = (long long)NE1 * (H_F / 4);
        scatter_add_kernel<<<(int)((total + 255) / 256), 256>>>(
            h, e1_src, e1_dst, agg2, deg2, NE1, H_F);
        total = (long long)NDST1 * (H_F / 4);
        normalize_kernel<<<(int)((total + 255) / 256), 256>>>(agg2, deg2, NDST1, H_F);
    }
    // 6. layer-2 dual-GEMM + bias -> out [5000,256]
    {
        dim3 grid(N_CLS / 128, (NDST1 + 127) / 128);
        sage_mma_gemm<<<grid, 256>>>(
            h, agg2, w2s_hi, w2s_lo, w2n_hi, w2n_lo, b2, out, NDST1, N_CLS, H_F, 0);
    }
}

// round 5
// speedup vs baseline: 1.9260x; 1.1368x over previous
#include <cuda_runtime.h>
#include <cuda_bf16.h>
#include <cstdint>

#define NSRC0 100000
#define NDST0 20000
#define NDST1 5000
#define NE0   160000
#define NE1   40000
#define IN_F  512
#define H_F   1024
#define N_CLS 256

#define APAD 40   // bf16 elems per smem row (32 data + 8 pad) -> 80B stride

// ---------------------------------------------------------------------------
// Scratch (device globals: allocation-free per harness rules)
// ---------------------------------------------------------------------------
__device__ __align__(16) float g_agg1[(long long)NDST0 * IN_F];
__device__ float g_deg1[NDST0];
__device__ __align__(16) float g_h[(long long)NDST0 * H_F];
__device__ __align__(16) float g_agg2[(long long)NDST1 * H_F];
__device__ float g_deg2[NDST1];

// bf16 hi/lo split operands
__device__ __align__(16) __nv_bfloat16 g_xhi[(long long)NDST0 * IN_F];
__device__ __align__(16) __nv_bfloat16 g_xlo[(long long)NDST0 * IN_F];
__device__ __align__(16) __nv_bfloat16 g_a1hi[(long long)NDST0 * IN_F];
__device__ __align__(16) __nv_bfloat16 g_a1lo[(long long)NDST0 * IN_F];
__device__ __align__(16) __nv_bfloat16 g_hhi[(long long)NDST1 * H_F];
__device__ __align__(16) __nv_bfloat16 g_hlo[(long long)NDST1 * H_F];
__device__ __align__(16) __nv_bfloat16 g_a2hi[(long long)NDST1 * H_F];
__device__ __align__(16) __nv_bfloat16 g_a2lo[(long long)NDST1 * H_F];

// Pre-transposed, bf16-split weights: [N, K] layout
__device__ __align__(16) __nv_bfloat16 g_w1s_hi[H_F * IN_F];
__device__ __align__(16) __nv_bfloat16 g_w1s_lo[H_F * IN_F];
__device__ __align__(16) __nv_bfloat16 g_w1n_hi[H_F * IN_F];
__device__ __align__(16) __nv_bfloat16 g_w1n_lo[H_F * IN_F];
__device__ __align__(16) __nv_bfloat16 g_w2s_hi[N_CLS * H_F];
__device__ __align__(16) __nv_bfloat16 g_w2s_lo[N_CLS * H_F];
__device__ __align__(16) __nv_bfloat16 g_w2n_hi[N_CLS * H_F];
__device__ __align__(16) __nv_bfloat16 g_w2n_lo[N_CLS * H_F];

// ---------------------------------------------------------------------------
// helpers
// ---------------------------------------------------------------------------
__device__ __forceinline__ void cp16(uint32_t dst, const void* src, bool pred) {
    asm volatile("cp.async.cg.shared.global [%0], [%1], 16, %2;"
                 :: "r"(dst), "l"(src), "r"(pred ? 16 : 0));
}
__device__ __forceinline__ void split2(float x, float y,
                                       uint32_t& hi, uint32_t& lo) {
    __nv_bfloat16 hx = __float2bfloat16(x);
    __nv_bfloat16 hy = __float2bfloat16(y);
    __nv_bfloat16 lx = __float2bfloat16(x - __bfloat162float(hx));
    __nv_bfloat16 ly = __float2bfloat16(y - __bfloat162float(hy));
    hi = ((uint32_t)__bfloat16_as_ushort(hy) << 16) | __bfloat16_as_ushort(hx);
    lo = ((uint32_t)__bfloat16_as_ushort(ly) << 16) | __bfloat16_as_ushort(lx);
}
__device__ __forceinline__ void mma16816(float* c, uint32_t a0, uint32_t a1,
                                         uint32_t a2, uint32_t a3,
                                         uint32_t b0, uint32_t b1) {
    asm volatile(
        "mma.sync.aligned.m16n8k16.row.col.f32.bf16.bf16.f32 "
        "{%0,%1,%2,%3}, {%4,%5,%6,%7}, {%8,%9}, {%0,%1,%2,%3};"
        : "+f"(c[0]), "+f"(c[1]), "+f"(c[2]), "+f"(c[3])
        : "r"(a0), "r"(a1), "r"(a2), "r"(a3), "r"(b0), "r"(b1));
}

// ---------------------------------------------------------------------------
// Zero accumulators
// ---------------------------------------------------------------------------
__global__ void zero_all_kernel() {
    long long i = (long long)blockIdx.x * blockDim.x + threadIdx.x;
    if (i < (long long)NDST0 * IN_F) g_agg1[i] = 0.0f;
    if (i < (long long)NDST1 * H_F)  g_agg2[i] = 0.0f;
    if (i < NDST0) g_deg1[i] = 0.0f;
    if (i < NDST1) g_deg2[i] = 0.0f;
}

// ---------------------------------------------------------------------------
// Transpose + bf16 hi/lo split: W[K,N] row-major -> hi/lo [N,K]
// ---------------------------------------------------------------------------
__global__ void transpose_split_kernel(const float* __restrict__ W,
                                       __nv_bfloat16* __restrict__ hi,
                                       __nv_bfloat16* __restrict__ lo,
                                       int K, int N) {
    __shared__ float t[32][33];
    int n0 = blockIdx.x * 32, k0 = blockIdx.y * 32;
    int tx = threadIdx.x, ty = threadIdx.y;
#pragma unroll
    for (int i = 0; i < 4; i++)
        t[ty + 8 * i][tx] = W[(long long)(k0 + ty + 8 * i) * N + n0 + tx];
    __syncthreads();
#pragma unroll
    for (int i = 0; i < 4; i++) {
        float v = t[tx][ty + 8 * i];
        __nv_bfloat16 h = __float2bfloat16(v);
        __nv_bfloat16 l = __float2bfloat16(v - __bfloat162float(h));
        long long o = (long long)(n0 + ty + 8 * i) * K + k0 + tx;
        hi[o] = h;
        lo[o] = l;
    }
}

// ---------------------------------------------------------------------------
// Elementwise fp32 -> bf16 hi/lo split (for x[:NDST0])
// ---------------------------------------------------------------------------
__global__ void split_rows_kernel(const float* __restrict__ src,
                                  __nv_bfloat16* __restrict__ hi,
                                  __nv_bfloat16* __restrict__ lo,
                                  long long n4) {
    long long i = (long long)blockIdx.x * blockDim.x + threadIdx.x;
    if (i >= n4) return;
    float4 v = reinterpret_cast<const float4*>(src)[i];
    uint32_t h01, l01, h23, l23;
    split2(v.x, v.y, h01, l01);
    split2(v.z, v.w, h23, l23);
    reinterpret_cast<uint2*>(hi)[i] = make_uint2(h01, h23);
    reinterpret_cast<uint2*>(lo)[i] = make_uint2(l01, l23);
}

// ---------------------------------------------------------------------------
// Edge scatter-add
// ---------------------------------------------------------------------------
__global__ void scatter_add_kernel(const float* __restrict__ feat,
                                   const int* __restrict__ esrc,
                                   const int* __restrict__ edst,
                                   float* __restrict__ agg,
                                   float* __restrict__ deg,
                                   int E, int F) {
    int idx = blockIdx.x * blockDim.x + threadIdx.x;
    int c4 = F >> 2;
    int e = idx / c4;
    if (e >= E) return;
    int c = idx - e * c4;
    int src = esrc[e];
    int dst = edst[e];
    float4 v = reinterpret_cast<const float4*>(feat)[(long long)src * c4 + c];
    float* a = agg + (long long)dst * F + (c << 2);
    atomicAdd(a + 0, v.x);
    atomicAdd(a + 1, v.y);
    atomicAdd(a + 2, v.z);
    atomicAdd(a + 3, v.w);
    if (c == 0) atomicAdd(deg + dst, 1.0f);
}

// ---------------------------------------------------------------------------
// Normalize by degree + split to bf16 hi/lo (no fp32 writeback)
// ---------------------------------------------------------------------------
__global__ void normalize_split_kernel(const float* __restrict__ agg,
                                       const float* __restrict__ deg,
                                       __nv_bfloat16* __restrict__ hi,
                                       __nv_bfloat16* __restrict__ lo,
                                       int rows, int F) {
    int idx = blockIdx.x * blockDim.x + threadIdx.x;
    int c4 = F >> 2;
    int r = idx / c4;
    if (r >= rows) return;
    float s = 1.0f / fmaxf(deg[r], 1.0f);
    float4 v = reinterpret_cast<const float4*>(agg)[idx];
    v.x *= s; v.y *= s; v.z *= s; v.w *= s;
    uint32_t h01, l01, h23, l23;
    split2(v.x, v.y, h01, l01);
    split2(v.z, v.w, h23, l23);
    reinterpret_cast<uint2*>(hi)[idx] = make_uint2(h01, h23);
    reinterpret_cast<uint2*>(lo)[idx] = make_uint2(l01, l23);
}

// ---------------------------------------------------------------------------
// Pipelined dual-pair split-bf16 tensor-core GEMM:
//   C = act( A0 @ B0^T + A1 @ B1^T + bias ),  C += Ahi*Bhi + Ahi*Blo + Alo*Bhi
// A hi/lo: [M,K] bf16 (pre-split). B hi/lo: [N,K] bf16.
// NW_N = warps along N. BM = 32*(8/NW_N) (128 or 64), BN = 128, BK = 32.
// 2-stage cp.async double buffer.
// ---------------------------------------------------------------------------
template <int NW_N>
__global__ void __launch_bounds__(256)
sage_mma_gemm(const __nv_bfloat16* __restrict__ A0hi, const __nv_bfloat16* __restrict__ A0lo,
              const __nv_bfloat16* __restrict__ A1hi, const __nv_bfloat16* __restrict__ A1lo,
              const __nv_bfloat16* __restrict__ B0hi, const __nv_bfloat16* __restrict__ B0lo,
              const __nv_bfloat16* __restrict__ B1hi, const __nv_bfloat16* __restrict__ B1lo,
              const float* __restrict__ bias, float* __restrict__ C,
              __nv_bfloat16* __restrict__ Chi, __nv_bfloat16* __restrict__ Clo,
              int splitRows, int M, int N, int K, int doRelu) {
    constexpr int BM = 32 * (8 / NW_N);      // 128 | 64
    constexpr int NJ = 128 / (8 * NW_N);     // 8 | 4  (n8 tiles per warp)
    constexpr int ATILE = BM * APAD;         // elems
    constexpr int BTILE = 128 * APAD;
    constexpr int SSTRIDE = 2 * ATILE + 2 * BTILE;  // elems per stage

    extern __shared__ __nv_bfloat16 sm[];
    uint32_t sbase = (uint32_t)__cvta_generic_to_shared(sm);

    int tid = threadIdx.x;
    int wid = tid >> 5;
    int lane = tid & 31;
    int g = lane >> 2;
    int t = lane & 3;
    int warpM = wid / NW_N;
    int warpN = wid % NW_N;
    int rowC = blockIdx.y * BM;
    int colC = blockIdx.x * 128;

    const int nk = K >> 5;           // chunks per pass
    const int total = 2 * nk;

    auto issue = [&](int q, int s) {
        int pass = q >= nk;
        int k0 = (pass ? q - nk : q) << 5;
        const __nv_bfloat16* Ah = pass ? A1hi : A0hi;
        const __nv_bfloat16* Al = pass ? A1lo : A0lo;
        const __nv_bfloat16* Bh = pass ? B1hi : B0hi;
        const __nv_bfloat16* Bl = pass ? B1lo : B0lo;
        uint32_t sb = sbase + (uint32_t)s * (SSTRIDE * 2);
#pragma unroll
        for (int it = 0; it < BM / 64; it++) {
            int u = tid + it * 256;          // < BM*4
            int r = u >> 2, c = u & 3;
            int gr = rowC + r;
            bool p = gr < M;
            long long go = (long long)(p ? gr : 0) * K + k0 + (c << 3);
            uint32_t off = (uint32_t)(r * APAD + (c << 3)) * 2;
            cp16(sb + off, Ah + go, p);
            cp16(sb + ATILE * 2 + off, Al + go, p);
        }
#pragma unroll
        for (int it = 0; it < 2; it++) {
            int u = tid + it * 256;          // < 512
            int r = u >> 2, c = u & 3;
            long long go = (long long)(colC + r) * K + k0 + (c << 3);
            uint32_t off = (uint32_t)(r * APAD + (c << 3)) * 2;
            cp16(sb + 2 * ATILE * 2 + off, Bh + go, true);
            cp16(sb + (2 * ATILE + BTILE) * 2 + off, Bl + go, true);
        }
        asm volatile("cp.async.commit_group;" ::: "memory");
    };

    float acc[2][NJ][4];
#pragma unroll
    for (int i = 0; i < 2; i++)
#pragma unroll
        for (int j = 0; j < NJ; j++)
#pragma unroll
            for (int q = 0; q < 4; q++) acc[i][j][q] = 0.0f;

    issue(0, 0);

#pragma unroll 1
    for (int q = 0; q < total; q++) {
        int s = q & 1;
        if (q + 1 < total) {
            issue(q + 1, s ^ 1);
            asm volatile("cp.async.wait_group 1;" ::: "memory");
        } else {
            asm volatile("cp.async.wait_group 0;" ::: "memory");
        }
        __syncthreads();

        const __nv_bfloat16* base = sm + s * SSTRIDE;
        const __nv_bfloat16* sAhi = base;
        const __nv_bfloat16* sAlo = base + ATILE;
        const __nv_bfloat16* sBhi = base + 2 * ATILE;
        const __nv_bfloat16* sBlo = base + 2 * ATILE + BTILE;

#pragma unroll
        for (int s3 = 0; s3 < 3; s3++) {
            const __nv_bfloat16* As = (s3 == 2) ? sAlo : sAhi;
            const __nv_bfloat16* Bs = (s3 == 1) ? sBlo : sBhi;
#pragma unroll
            for (int ks = 0; ks < 2; ks++) {
                int kb = ks * 16 + 2 * t;
                uint32_t a[2][4];
#pragma unroll
                for (int i = 0; i < 2; i++) {
                    int r0 = warpM * 32 + i * 16 + g;
                    a[i][0] = *reinterpret_cast<const uint32_t*>(&As[r0 * APAD + kb]);
                    a[i][1] = *reinterpret_cast<const uint32_t*>(&As[(r0 + 8) * APAD + kb]);
                    a[i][2] = *reinterpret_cast<const uint32_t*>(&As[r0 * APAD + kb + 8]);
                    a[i][3] = *reinterpret_cast<const uint32_t*>(&As[(r0 + 8) * APAD + kb + 8]);
                }
                uint32_t b[NJ][2];
#pragma unroll
                for (int j = 0; j < NJ; j++) {
                    int n0 = warpN * (NJ * 8) + j * 8 + g;
                    b[j][0] = *reinterpret_cast<const uint32_t*>(&Bs[n0 * APAD + kb]);
                    b[j][1] = *reinterpret_cast<const uint32_t*>(&Bs[n0 * APAD + kb + 8]);
                }
#pragma unroll
                for (int i = 0; i < 2; i++)
#pragma unroll
                    for (int j = 0; j < NJ; j++)
                        mma16816(acc[i][j], a[i][0], a[i][1], a[i][2], a[i][3],
                                 b[j][0], b[j][1]);
            }
        }
        __syncthreads();
    }

    // --- epilogue: bias (+ReLU); optional bf16 hi/lo split write ---
#pragma unroll
    for (int i = 0; i < 2; i++) {
#pragma unroll
        for (int j = 0; j < NJ; j++) {
            int row = rowC + warpM * 32 + i * 16 + g;
            int col = colC + warpN * (NJ * 8) + j * 8 + 2 * t;
            float bx = bias[col], by = bias[col + 1];
            float2 v0, v1;
            v0.x = acc[i][j][0] + bx; v0.y = acc[i][j][1] + by;
            v1.x = acc[i][j][2] + bx; v1.y = acc[i][j][3] + by;
            if (doRelu) {
                v0.x = fmaxf(v0.x, 0.f); v0.y = fmaxf(v0.y, 0.f);
                v1.x = fmaxf(v1.x, 0.f); v1.y = fmaxf(v1.y, 0.f);
            }
            if (row < M)
                *reinterpret_cast<float2*>(C + (long long)row * N + col) = v0;
            if (row + 8 < M)
                *reinterpret_cast<float2*>(C + (long long)(row + 8) * N + col) = v1;
            if (Chi) {
                if (row < splitRows) {
                    uint32_t h, l;
                    split2(v0.x, v0.y, h, l);
                    *reinterpret_cast<uint32_t*>(Chi + (long long)row * N + col) = h;
                    *reinterpret_cast<uint32_t*>(Clo + (long long)row * N + col) = l;
                }
                if (row + 8 < splitRows) {
                    uint32_t h, l;
                    split2(v1.x, v1.y, h, l);
                    *reinterpret_cast<uint32_t*>(Chi + (long long)(row + 8) * N + col) = h;
                    *reinterpret_cast<uint32_t*>(Clo + (long long)(row + 8) * N + col) = l;
                }
            }
        }
    }
}

// ---------------------------------------------------------------------------
extern "C" void kernel_launch(void* const* d_in, const int* in_sizes, int n_in,
                              void* d_out, int out_size) {
    const float* x        = (const float*)d_in[0];
    const float* W_self1  = (const float*)d_in[1];
    const float* W_neigh1 = (const float*)d_in[2];
    const float* b1       = (const float*)d_in[3];
    const float* W_self2  = (const float*)d_in[4];
    const float* W_neigh2 = (const float*)d_in[5];
    const float* b2       = (const float*)d_in[6];
    const int*   e0_src   = (const int*)d_in[7];
    const int*   e0_dst   = (const int*)d_in[8];
    const int*   e1_src   = (const int*)d_in[9];
    const int*   e1_dst   = (const int*)d_in[10];
    float* out = (float*)d_out;

    float *agg1, *deg1, *h, *agg2, *deg2;
    cudaGetSymbolAddress((void**)&agg1, g_agg1);
    cudaGetSymbolAddress((void**)&deg1, g_deg1);
    cudaGetSymbolAddress((void**)&h,    g_h);
    cudaGetSymbolAddress((void**)&agg2, g_agg2);
    cudaGetSymbolAddress((void**)&deg2, g_deg2);
    __nv_bfloat16 *xhi, *xlo, *a1hi, *a1lo, *hhi, *hlo, *a2hi, *a2lo;
    cudaGetSymbolAddress((void**)&xhi,  g_xhi);
    cudaGetSymbolAddress((void**)&xlo,  g_xlo);
    cudaGetSymbolAddress((void**)&a1hi, g_a1hi);
    cudaGetSymbolAddress((void**)&a1lo, g_a1lo);
    cudaGetSymbolAddress((void**)&hhi,  g_hhi);
    cudaGetSymbolAddress((void**)&hlo,  g_hlo);
    cudaGetSymbolAddress((void**)&a2hi, g_a2hi);
    cudaGetSymbolAddress((void**)&a2lo, g_a2lo);
    __nv_bfloat16 *w1s_hi, *w1s_lo, *w1n_hi, *w1n_lo, *w2s_hi, *w2s_lo, *w2n_hi, *w2n_lo;
    cudaGetSymbolAddress((void**)&w1s_hi, g_w1s_hi);
    cudaGetSymbolAddress((void**)&w1s_lo, g_w1s_lo);
    cudaGetSymbolAddress((void**)&w1n_hi, g_w1n_hi);
    cudaGetSymbolAddress((void**)&w1n_lo, g_w1n_lo);
    cudaGetSymbolAddress((void**)&w2s_hi, g_w2s_hi);
    cudaGetSymbolAddress((void**)&w2s_lo, g_w2s_lo);
    cudaGetSymbolAddress((void**)&w2n_hi, g_w2n_hi);
    cudaGetSymbolAddress((void**)&w2n_lo, g_w2n_lo);

    constexpr int SMEM1 = (2 * (2 * 128 * APAD + 2 * 128 * APAD)) * 2;  // 81920B
    constexpr int SMEM2 = (2 * (2 * 64 * APAD + 2 * 128 * APAD)) * 2;   // 61440B
    static bool attr_set = false;
    if (!attr_set) {
        cudaFuncSetAttribute(sage_mma_gemm<2>, cudaFuncAttributeMaxDynamicSharedMemorySize, SMEM1);
        cudaFuncSetAttribute(sage_mma_gemm<4>, cudaFuncAttributeMaxDynamicSharedMemorySize, SMEM2);
        attr_set = true;
    }

    // 1. zero accumulators
    {
        long long mx = (long long)NDST0 * IN_F;
        zero_all_kernel<<<(int)((mx + 255) / 256), 256>>>();
    }
    // 2. weight transpose + bf16 split; x[:NDST0] split
    {
        dim3 b(32, 8);
        transpose_split_kernel<<<dim3(H_F / 32, IN_F / 32), b>>>(W_self1,  w1s_hi, w1s_lo, IN_F, H_F);
        transpose_split_kernel<<<dim3(H_F / 32, IN_F / 32), b>>>(W_neigh1, w1n_hi, w1n_lo, IN_F, H_F);
        transpose_split_kernel<<<dim3(N_CLS / 32, H_F / 32), b>>>(W_self2,  w2s_hi, w2s_lo, H_F, N_CLS);
        transpose_split_kernel<<<dim3(N_CLS / 32, H_F / 32), b>>>(W_neigh2, w2n_hi, w2n_lo, H_F, N_CLS);
        long long n4 = (long long)NDST0 * IN_F / 4;
        split_rows_kernel<<<(int)((n4 + 255) / 256), 256>>>(x, xhi, xlo, n4);
    }
    // 3. layer-1 scatter + normalize-split
    {
        long long total = (long long)NE0 * (IN_F / 4);
        scatter_add_kernel<<<(int)((total + 255) / 256), 256>>>(
            x, e0_src, e0_dst, agg1, deg1, NE0, IN_F);
        total = (long long)NDST0 * (IN_F / 4);
        normalize_split_kernel<<<(int)((total + 255) / 256), 256>>>(
            agg1, deg1, a1hi, a1lo, NDST0, IN_F);
    }
    // 4. layer-1 dual-GEMM + bias + ReLU -> h fp32 (+ hi/lo split of h[:NDST1])
    {
        dim3 grid(H_F / 128, (NDST0 + 127) / 128);
        sage_mma_gemm<2><<<grid, 256, SMEM1>>>(
            xhi, xlo, a1hi, a1lo, w1s_hi, w1s_lo, w1n_hi, w1n_lo,
            b1, h, hhi, hlo, NDST1, NDST0, H_F, IN_F, 1);
    }
    // 5. layer-2 scatter + normalize-split
    {
        long long total = (long long)NE1 * (H_F / 4);
        scatter_add_kernel<<<(int)((total + 255) / 256), 256>>>(
            h, e1_src, e1_dst, agg2, deg2, NE1, H_F);
        total = (long long)NDST1 * (H_F / 4);
        normalize_split_kernel<<<(int)((total + 255) / 256), 256>>>(
            agg2, deg2, a2hi, a2lo, NDST1, H_F);
    }
    // 6. layer-2 dual-GEMM + bias -> out [5000,256]  (BM=64 tile, 158 CTAs)
    {
        dim3 grid(N_CLS / 128, (NDST1 + 63) / 64);
        sage_mma_gemm<4><<<grid, 256, SMEM2>>>(
            hhi, hlo, a2hi, a2lo, w2s_hi, w2s_lo, w2n_hi, w2n_lo,
            b2, out, nullptr, nullptr, 0, NDST1, N_CLS, H_F, 0);
    }
}

// round 6
// speedup vs baseline: 2.5777x; 1.3384x over previous
#include <cuda_runtime.h>
#include <cuda_bf16.h>
#include <cstdint>

#define NSRC0 100000
#define NDST0 20000
#define NDST1 5000
#define NE0   160000
#define NE1   40000
#define IN_F  512
#define H_F   1024
#define N_CLS 256

#define APAD 40   // bf16 elems per smem row (32 data + 8 pad) -> 80B stride

// ---------------------------------------------------------------------------
// Scratch (device globals: allocation-free per harness rules)
// ---------------------------------------------------------------------------
__device__ __align__(16) float g_h[(long long)NDST0 * H_F];

// bf16 hi/lo split operands
__device__ __align__(16) __nv_bfloat16 g_xhi[(long long)NDST0 * IN_F];
__device__ __align__(16) __nv_bfloat16 g_xlo[(long long)NDST0 * IN_F];
__device__ __align__(16) __nv_bfloat16 g_a1hi[(long long)NDST0 * IN_F];
__device__ __align__(16) __nv_bfloat16 g_a1lo[(long long)NDST0 * IN_F];
__device__ __align__(16) __nv_bfloat16 g_hhi[(long long)NDST1 * H_F];
__device__ __align__(16) __nv_bfloat16 g_hlo[(long long)NDST1 * H_F];
__device__ __align__(16) __nv_bfloat16 g_a2hi[(long long)NDST1 * H_F];
__device__ __align__(16) __nv_bfloat16 g_a2lo[(long long)NDST1 * H_F];

// CSR scratch
__device__ int g_cnt0[NDST0];
__device__ int g_off0[NDST0 + 1];
__device__ int g_cur0[NDST0];
__device__ int g_eidx0[NE0];
__device__ int g_cnt1[NDST1];
__device__ int g_off1[NDST1 + 1];
__device__ int g_cur1[NDST1];
__device__ int g_eidx1[NE1];

// Pre-transposed, bf16-split weights: [N, K] layout
__device__ __align__(16) __nv_bfloat16 g_w1s_hi[H_F * IN_F];
__device__ __align__(16) __nv_bfloat16 g_w1s_lo[H_F * IN_F];
__device__ __align__(16) __nv_bfloat16 g_w1n_hi[H_F * IN_F];
__device__ __align__(16) __nv_bfloat16 g_w1n_lo[H_F * IN_F];
__device__ __align__(16) __nv_bfloat16 g_w2s_hi[N_CLS * H_F];
__device__ __align__(16) __nv_bfloat16 g_w2s_lo[N_CLS * H_F];
__device__ __align__(16) __nv_bfloat16 g_w2n_hi[N_CLS * H_F];
__device__ __align__(16) __nv_bfloat16 g_w2n_lo[N_CLS * H_F];

// ---------------------------------------------------------------------------
// helpers
// ---------------------------------------------------------------------------
__device__ __forceinline__ void cp16(uint32_t dst, const void* src, bool pred) {
    asm volatile("cp.async.cg.shared.global [%0], [%1], 16, %2;"
                 :: "r"(dst), "l"(src), "r"(pred ? 16 : 0));
}
__device__ __forceinline__ void split2(float x, float y,
                                       uint32_t& hi, uint32_t& lo) {
    __nv_bfloat16 hx = __float2bfloat16(x);
    __nv_bfloat16 hy = __float2bfloat16(y);
    __nv_bfloat16 lx = __float2bfloat16(x - __bfloat162float(hx));
    __nv_bfloat16 ly = __float2bfloat16(y - __bfloat162float(hy));
    hi = ((uint32_t)__bfloat16_as_ushort(hy) << 16) | __bfloat16_as_ushort(hx);
    lo = ((uint32_t)__bfloat16_as_ushort(ly) << 16) | __bfloat16_as_ushort(lx);
}
__device__ __forceinline__ void mma16816(float* c, uint32_t a0, uint32_t a1,
                                         uint32_t a2, uint32_t a3,
                                         uint32_t b0, uint32_t b1) {
    asm volatile(
        "mma.sync.aligned.m16n8k16.row.col.f32.bf16.bf16.f32 "
        "{%0,%1,%2,%3}, {%4,%5,%6,%7}, {%8,%9}, {%0,%1,%2,%3};"
        : "+f"(c[0]), "+f"(c[1]), "+f"(c[2]), "+f"(c[3])
        : "r"(a0), "r"(a1), "r"(a2), "r"(a3), "r"(b0), "r"(b1));
}

// ---------------------------------------------------------------------------
// CSR build
// ---------------------------------------------------------------------------
__global__ void zero_counts_kernel() {
    int i = blockIdx.x * blockDim.x + threadIdx.x;
    if (i < NDST0) g_cnt0[i] = 0;
    if (i < NDST1) g_cnt1[i] = 0;
}
__global__ void count_kernel(const int* __restrict__ edst, int* __restrict__ cnt, int E) {
    int e = blockIdx.x * blockDim.x + threadIdx.x;
    if (e < E) atomicAdd(&cnt[edst[e]], 1);
}
// One CTA per layer: exclusive scan of counts -> off, cur; off[n] = total.
__global__ void __launch_bounds__(1024) scan_kernel() {
    const int n   = blockIdx.x == 0 ? NDST0 : NDST1;
    int* cnt = blockIdx.x == 0 ? g_cnt0 : g_cnt1;
    int* off = blockIdx.x == 0 ? g_off0 : g_off1;
    int* cur = blockIdx.x == 0 ? g_cur0 : g_cur1;
    __shared__ int part[1024];
    int tid = threadIdx.x;
    int chunk = (n + 1023) >> 10;
    int beg = tid * chunk, end = min(beg + chunk, n);
    int s = 0;
    for (int i = beg; i < end; i++) s += cnt[i];
    part[tid] = s;
    __syncthreads();
    for (int d = 1; d < 1024; d <<= 1) {
        int v = (tid >= d) ? part[tid - d] : 0;
        __syncthreads();
        part[tid] += v;
        __syncthreads();
    }
    int prefix = tid ? part[tid - 1] : 0;
    for (int i = beg; i < end; i++) {
        off[i] = prefix;
        cur[i] = prefix;
        prefix += cnt[i];
    }
    if (tid == 0) off[n] = part[1023];
}
__global__ void fill_kernel(const int* __restrict__ esrc, const int* __restrict__ edst,
                            int* __restrict__ cur, int* __restrict__ eidx, int E) {
    int e = blockIdx.x * blockDim.x + threadIdx.x;
    if (e >= E) return;
    int p = atomicAdd(&cur[edst[e]], 1);
    eidx[p] = esrc[e];
}

// ---------------------------------------------------------------------------
// Gather-mean + bf16 split: one CTA per dst row, F/4 threads (float4 each)
// ---------------------------------------------------------------------------
template <int F>
__global__ void __launch_bounds__(F / 4)
gather_mean_split(const float* __restrict__ feat,
                  const int* __restrict__ off, const int* __restrict__ eidx,
                  __nv_bfloat16* __restrict__ hi, __nv_bfloat16* __restrict__ lo) {
    int row = blockIdx.x;
    int tid = threadIdx.x;
    int beg = off[row], end = off[row + 1];
    float4 acc = make_float4(0.f, 0.f, 0.f, 0.f);
    int j = beg;
    for (; j + 2 <= end; j += 2) {       // 2-way unroll for MLP
        int s0 = eidx[j], s1 = eidx[j + 1];
        float4 v0 = reinterpret_cast<const float4*>(feat)[(long long)s0 * (F / 4) + tid];
        float4 v1 = reinterpret_cast<const float4*>(feat)[(long long)s1 * (F / 4) + tid];
        acc.x += v0.x + v1.x; acc.y += v0.y + v1.y;
        acc.z += v0.z + v1.z; acc.w += v0.w + v1.w;
    }
    if (j < end) {
        float4 v = reinterpret_cast<const float4*>(feat)[(long long)eidx[j] * (F / 4) + tid];
        acc.x += v.x; acc.y += v.y; acc.z += v.z; acc.w += v.w;
    }
    float sc = 1.0f / (float)max(end - beg, 1);
    acc.x *= sc; acc.y *= sc; acc.z *= sc; acc.w *= sc;
    uint32_t h01, l01, h23, l23;
    split2(acc.x, acc.y, h01, l01);
    split2(acc.z, acc.w, h23, l23);
    long long o = (long long)row * (F / 4) + tid;
    reinterpret_cast<uint2*>(hi)[o] = make_uint2(h01, h23);
    reinterpret_cast<uint2*>(lo)[o] = make_uint2(l01, l23);
}

// ---------------------------------------------------------------------------
// Transpose + bf16 hi/lo split: W[K,N] row-major -> hi/lo [N,K]
// ---------------------------------------------------------------------------
__global__ void transpose_split_kernel(const float* __restrict__ W,
                                       __nv_bfloat16* __restrict__ hi,
                                       __nv_bfloat16* __restrict__ lo,
                                       int K, int N) {
    __shared__ float t[32][33];
    int n0 = blockIdx.x * 32, k0 = blockIdx.y * 32;
    int tx = threadIdx.x, ty = threadIdx.y;
#pragma unroll
    for (int i = 0; i < 4; i++)
        t[ty + 8 * i][tx] = W[(long long)(k0 + ty + 8 * i) * N + n0 + tx];
    __syncthreads();
#pragma unroll
    for (int i = 0; i < 4; i++) {
        float v = t[tx][ty + 8 * i];
        __nv_bfloat16 h = __float2bfloat16(v);
        __nv_bfloat16 l = __float2bfloat16(v - __bfloat162float(h));
        long long o = (long long)(n0 + ty + 8 * i) * K + k0 + tx;
        hi[o] = h;
        lo[o] = l;
    }
}

// ---------------------------------------------------------------------------
// Elementwise fp32 -> bf16 hi/lo split (for x[:NDST0])
// ---------------------------------------------------------------------------
__global__ void split_rows_kernel(const float* __restrict__ src,
                                  __nv_bfloat16* __restrict__ hi,
                                  __nv_bfloat16* __restrict__ lo,
                                  long long n4) {
    long long i = (long long)blockIdx.x * blockDim.x + threadIdx.x;
    if (i >= n4) return;
    float4 v = reinterpret_cast<const float4*>(src)[i];
    uint32_t h01, l01, h23, l23;
    split2(v.x, v.y, h01, l01);
    split2(v.z, v.w, h23, l23);
    reinterpret_cast<uint2*>(hi)[i] = make_uint2(h01, h23);
    reinterpret_cast<uint2*>(lo)[i] = make_uint2(l01, l23);
}

// ---------------------------------------------------------------------------
// Pipelined dual-pair split-bf16 tensor-core GEMM (unchanged from R5):
//   C = act( A0 @ B0^T + A1 @ B1^T + bias ),  C += Ahi*Bhi + Ahi*Blo + Alo*Bhi
// ---------------------------------------------------------------------------
template <int NW_N>
__global__ void __launch_bounds__(256)
sage_mma_gemm(const __nv_bfloat16* __restrict__ A0hi, const __nv_bfloat16* __restrict__ A0lo,
              const __nv_bfloat16* __restrict__ A1hi, const __nv_bfloat16* __restrict__ A1lo,
              const __nv_bfloat16* __restrict__ B0hi, const __nv_bfloat16* __restrict__ B0lo,
              const __nv_bfloat16* __restrict__ B1hi, const __nv_bfloat16* __restrict__ B1lo,
              const float* __restrict__ bias, float* __restrict__ C,
              __nv_bfloat16* __restrict__ Chi, __nv_bfloat16* __restrict__ Clo,
              int splitRows, int M, int N, int K, int doRelu) {
    constexpr int BM = 32 * (8 / NW_N);
    constexpr int NJ = 128 / (8 * NW_N);
    constexpr int ATILE = BM * APAD;
    constexpr int BTILE = 128 * APAD;
    constexpr int SSTRIDE = 2 * ATILE + 2 * BTILE;

    extern __shared__ __nv_bfloat16 sm[];
    uint32_t sbase = (uint32_t)__cvta_generic_to_shared(sm);

    int tid = threadIdx.x;
    int wid = tid >> 5;
    int lane = tid & 31;
    int g = lane >> 2;
    int t = lane & 3;
    int warpM = wid / NW_N;
    int warpN = wid % NW_N;
    int rowC = blockIdx.y * BM;
    int colC = blockIdx.x * 128;

    const int nk = K >> 5;
    const int total = 2 * nk;

    auto issue = [&](int q, int s) {
        int pass = q >= nk;
        int k0 = (pass ? q - nk : q) << 5;
        const __nv_bfloat16* Ah = pass ? A1hi : A0hi;
        const __nv_bfloat16* Al = pass ? A1lo : A0lo;
        const __nv_bfloat16* Bh = pass ? B1hi : B0hi;
        const __nv_bfloat16* Bl = pass ? B1lo : B0lo;
        uint32_t sb = sbase + (uint32_t)s * (SSTRIDE * 2);
#pragma unroll
        for (int it = 0; it < BM / 64; it++) {
            int u = tid + it * 256;
            int r = u >> 2, c = u & 3;
            int gr = rowC + r;
            bool p = gr < M;
            long long go = (long long)(p ? gr : 0) * K + k0 + (c << 3);
            uint32_t off = (uint32_t)(r * APAD + (c << 3)) * 2;
            cp16(sb + off, Ah + go, p);
            cp16(sb + ATILE * 2 + off, Al + go, p);
        }
#pragma unroll
        for (int it = 0; it < 2; it++) {
            int u = tid + it * 256;
            int r = u >> 2, c = u & 3;
            long long go = (long long)(colC + r) * K + k0 + (c << 3);
            uint32_t off = (uint32_t)(r * APAD + (c << 3)) * 2;
            cp16(sb + 2 * ATILE * 2 + off, Bh + go, true);
            cp16(sb + (2 * ATILE + BTILE) * 2 + off, Bl + go, true);
        }
        asm volatile("cp.async.commit_group;" ::: "memory");
    };

    float acc[2][NJ][4];
#pragma unroll
    for (int i = 0; i < 2; i++)
#pragma unroll
        for (int j = 0; j < NJ; j++)
#pragma unroll
            for (int q = 0; q < 4; q++) acc[i][j][q] = 0.0f;

    issue(0, 0);

#pragma unroll 1
    for (int q = 0; q < total; q++) {
        int s = q & 1;
        if (q + 1 < total) {
            issue(q + 1, s ^ 1);
            asm volatile("cp.async.wait_group 1;" ::: "memory");
        } else {
            asm volatile("cp.async.wait_group 0;" ::: "memory");
        }
        __syncthreads();

        const __nv_bfloat16* base = sm + s * SSTRIDE;
        const __nv_bfloat16* sAhi = base;
        const __nv_bfloat16* sAlo = base + ATILE;
        const __nv_bfloat16* sBhi = base + 2 * ATILE;
        const __nv_bfloat16* sBlo = base + 2 * ATILE + BTILE;

#pragma unroll
        for (int s3 = 0; s3 < 3; s3++) {
            const __nv_bfloat16* As = (s3 == 2) ? sAlo : sAhi;
            const __nv_bfloat16* Bs = (s3 == 1) ? sBlo : sBhi;
#pragma unroll
            for (int ks = 0; ks < 2; ks++) {
                int kb = ks * 16 + 2 * t;
                uint32_t a[2][4];
#pragma unroll
                for (int i = 0; i < 2; i++) {
                    int r0 = warpM * 32 + i * 16 + g;
                    a[i][0] = *reinterpret_cast<const uint32_t*>(&As[r0 * APAD + kb]);
                    a[i][1] = *reinterpret_cast<const uint32_t*>(&As[(r0 + 8) * APAD + kb]);
                    a[i][2] = *reinterpret_cast<const uint32_t*>(&As[r0 * APAD + kb + 8]);
                    a[i][3] = *reinterpret_cast<const uint32_t*>(&As[(r0 + 8) * APAD + kb + 8]);
                }
                uint32_t b[NJ][2];
#pragma unroll
                for (int j = 0; j < NJ; j++) {
                    int n0 = warpN * (NJ * 8) + j * 8 + g;
                    b[j][0] = *reinterpret_cast<const uint32_t*>(&Bs[n0 * APAD + kb]);
                    b[j][1] = *reinterpret_cast<const uint32_t*>(&Bs[n0 * APAD + kb + 8]);
                }
#pragma unroll
                for (int i = 0; i < 2; i++)
#pragma unroll
                    for (int j = 0; j < NJ; j++)
                        mma16816(acc[i][j], a[i][0], a[i][1], a[i][2], a[i][3],
                                 b[j][0], b[j][1]);
            }
        }
        __syncthreads();
    }

#pragma unroll
    for (int i = 0; i < 2; i++) {
#pragma unroll
        for (int j = 0; j < NJ; j++) {
            int row = rowC + warpM * 32 + i * 16 + g;
            int col = colC + warpN * (NJ * 8) + j * 8 + 2 * t;
            float bx = bias[col], by = bias[col + 1];
            float2 v0, v1;
            v0.x = acc[i][j][0] + bx; v0.y = acc[i][j][1] + by;
            v1.x = acc[i][j][2] + bx; v1.y = acc[i][j][3] + by;
            if (doRelu) {
                v0.x = fmaxf(v0.x, 0.f); v0.y = fmaxf(v0.y, 0.f);
                v1.x = fmaxf(v1.x, 0.f); v1.y = fmaxf(v1.y, 0.f);
            }
            if (row < M)
                *reinterpret_cast<float2*>(C + (long long)row * N + col) = v0;
            if (row + 8 < M)
                *reinterpret_cast<float2*>(C + (long long)(row + 8) * N + col) = v1;
            if (Chi) {
                if (row < splitRows) {
                    uint32_t h, l;
                    split2(v0.x, v0.y, h, l);
                    *reinterpret_cast<uint32_t*>(Chi + (long long)row * N + col) = h;
                    *reinterpret_cast<uint32_t*>(Clo + (long long)row * N + col) = l;
                }
                if (row + 8 < splitRows) {
                    uint32_t h, l;
                    split2(v1.x, v1.y, h, l);
                    *reinterpret_cast<uint32_t*>(Chi + (long long)(row + 8) * N + col) = h;
                    *reinterpret_cast<uint32_t*>(Clo + (long long)(row + 8) * N + col) = l;
                }
            }
        }
    }
}

// ---------------------------------------------------------------------------
extern "C" void kernel_launch(void* const* d_in, const int* in_sizes, int n_in,
                              void* d_out, int out_size) {
    const float* x        = (const float*)d_in[0];
    const float* W_self1  = (const float*)d_in[1];
    const float* W_neigh1 = (const float*)d_in[2];
    const float* b1       = (const float*)d_in[3];
    const float* W_self2  = (const float*)d_in[4];
    const float* W_neigh2 = (const float*)d_in[5];
    const float* b2       = (const float*)d_in[6];
    const int*   e0_src   = (const int*)d_in[7];
    const int*   e0_dst   = (const int*)d_in[8];
    const int*   e1_src   = (const int*)d_in[9];
    const int*   e1_dst   = (const int*)d_in[10];
    float* out = (float*)d_out;

    float* h;
    cudaGetSymbolAddress((void**)&h, g_h);
    __nv_bfloat16 *xhi, *xlo, *a1hi, *a1lo, *hhi, *hlo, *a2hi, *a2lo;
    cudaGetSymbolAddress((void**)&xhi,  g_xhi);
    cudaGetSymbolAddress((void**)&xlo,  g_xlo);
    cudaGetSymbolAddress((void**)&a1hi, g_a1hi);
    cudaGetSymbolAddress((void**)&a1lo, g_a1lo);
    cudaGetSymbolAddress((void**)&hhi,  g_hhi);
    cudaGetSymbolAddress((void**)&hlo,  g_hlo);
    cudaGetSymbolAddress((void**)&a2hi, g_a2hi);
    cudaGetSymbolAddress((void**)&a2lo, g_a2lo);
    __nv_bfloat16 *w1s_hi, *w1s_lo, *w1n_hi, *w1n_lo, *w2s_hi, *w2s_lo, *w2n_hi, *w2n_lo;
    cudaGetSymbolAddress((void**)&w1s_hi, g_w1s_hi);
    cudaGetSymbolAddress((void**)&w1s_lo, g_w1s_lo);
    cudaGetSymbolAddress((void**)&w1n_hi, g_w1n_hi);
    cudaGetSymbolAddress((void**)&w1n_lo, g_w1n_lo);
    cudaGetSymbolAddress((void**)&w2s_hi, g_w2s_hi);
    cudaGetSymbolAddress((void**)&w2s_lo, g_w2s_lo);
    cudaGetSymbolAddress((void**)&w2n_hi, g_w2n_hi);
    cudaGetSymbolAddress((void**)&w2n_lo, g_w2n_lo);
    int *cnt0, *off0, *cur0, *eidx0, *cnt1, *off1, *cur1, *eidx1;
    cudaGetSymbolAddress((void**)&cnt0, g_cnt0);
    cudaGetSymbolAddress((void**)&off0, g_off0);
    cudaGetSymbolAddress((void**)&cur0, g_cur0);
    cudaGetSymbolAddress((void**)&eidx0, g_eidx0);
    cudaGetSymbolAddress((void**)&cnt1, g_cnt1);
    cudaGetSymbolAddress((void**)&off1, g_off1);
    cudaGetSymbolAddress((void**)&cur1, g_cur1);
    cudaGetSymbolAddress((void**)&eidx1, g_eidx1);

    constexpr int SMEM1 = (2 * (2 * 128 * APAD + 2 * 128 * APAD)) * 2;
    constexpr int SMEM2 = (2 * (2 * 64 * APAD + 2 * 128 * APAD)) * 2;
    static bool attr_set = false;
    if (!attr_set) {
        cudaFuncSetAttribute(sage_mma_gemm<2>, cudaFuncAttributeMaxDynamicSharedMemorySize, SMEM1);
        cudaFuncSetAttribute(sage_mma_gemm<4>, cudaFuncAttributeMaxDynamicSharedMemorySize, SMEM2);
        attr_set = true;
    }

    // 1. CSR build (both layers)
    zero_counts_kernel<<<(NDST0 + 255) / 256, 256>>>();
    count_kernel<<<(NE0 + 255) / 256, 256>>>(e0_dst, cnt0, NE0);
    count_kernel<<<(NE1 + 255) / 256, 256>>>(e1_dst, cnt1, NE1);
    scan_kernel<<<2, 1024>>>();
    fill_kernel<<<(NE0 + 255) / 256, 256>>>(e0_src, e0_dst, cur0, eidx0, NE0);
    fill_kernel<<<(NE1 + 255) / 256, 256>>>(e1_src, e1_dst, cur1, eidx1, NE1);

    // 2. weight transpose + bf16 split; x[:NDST0] split
    {
        dim3 b(32, 8);
        transpose_split_kernel<<<dim3(H_F / 32, IN_F / 32), b>>>(W_self1,  w1s_hi, w1s_lo, IN_F, H_F);
        transpose_split_kernel<<<dim3(H_F / 32, IN_F / 32), b>>>(W_neigh1, w1n_hi, w1n_lo, IN_F, H_F);
        transpose_split_kernel<<<dim3(N_CLS / 32, H_F / 32), b>>>(W_self2,  w2s_hi, w2s_lo, H_F, N_CLS);
        transpose_split_kernel<<<dim3(N_CLS / 32, H_F / 32), b>>>(W_neigh2, w2n_hi, w2n_lo, H_F, N_CLS);
        long long n4 = (long long)NDST0 * IN_F / 4;
        split_rows_kernel<<<(int)((n4 + 255) / 256), 256>>>(x, xhi, xlo, n4);
    }
    // 3. layer-1 gather-mean (atomic-free) -> a1 hi/lo
    gather_mean_split<IN_F><<<NDST0, IN_F / 4>>>(x, off0, eidx0, a1hi, a1lo);

    // 4. layer-1 dual-GEMM + bias + ReLU -> h fp32 (+ hi/lo split of h[:NDST1])
    {
        dim3 grid(H_F / 128, (NDST0 + 127) / 128);
        sage_mma_gemm<2><<<grid, 256, SMEM1>>>(
            xhi, xlo, a1hi, a1lo, w1s_hi, w1s_lo, w1n_hi, w1n_lo,
            b1, h, hhi, hlo, NDST1, NDST0, H_F, IN_F, 1);
    }
    // 5. layer-2 gather-mean -> a2 hi/lo
    gather_mean_split<H_F><<<NDST1, H_F / 4>>>(h, off1, eidx1, a2hi, a2lo);

    // 6. layer-2 dual-GEMM + bias -> out [5000,256]
    {
        dim3 grid(N_CLS / 128, (NDST1 + 63) / 64);
        sage_mma_gemm<4><<<grid, 256, SMEM2>>>(
            hhi, hlo, a2hi, a2lo, w2s_hi, w2s_lo, w2n_hi, w2n_lo,
            b2, out, nullptr, nullptr, 0, NDST1, N_CLS, H_F, 0);
    }
}

// round 7
// speedup vs baseline: 3.0425x; 1.1803x over previous
#include <cuda_runtime.h>
#include <cuda_bf16.h>
#include <cstdint>

#define NSRC0 100000
#define NDST0 20000
#define NDST1 5000
#define NE0   160000
#define NE1   40000
#define IN_F  512
#define H_F   1024
#define N_CLS 256

#define APAD 40   // bf16 elems per smem row (32 data + 8 pad) -> 80B stride

// ---------------------------------------------------------------------------
// Scratch (device globals: allocation-free per harness rules)
// ---------------------------------------------------------------------------
__device__ __align__(16) float g_h[(long long)NDST0 * H_F];

__device__ __align__(16) __nv_bfloat16 g_xhi[(long long)NDST0 * IN_F];
__device__ __align__(16) __nv_bfloat16 g_xlo[(long long)NDST0 * IN_F];
__device__ __align__(16) __nv_bfloat16 g_a1hi[(long long)NDST0 * IN_F];
__device__ __align__(16) __nv_bfloat16 g_a1lo[(long long)NDST0 * IN_F];
__device__ __align__(16) __nv_bfloat16 g_hhi[(long long)NDST1 * H_F];
__device__ __align__(16) __nv_bfloat16 g_hlo[(long long)NDST1 * H_F];
__device__ __align__(16) __nv_bfloat16 g_a2hi[(long long)NDST1 * H_F];
__device__ __align__(16) __nv_bfloat16 g_a2lo[(long long)NDST1 * H_F];

__device__ int g_cnt0[NDST0];
__device__ int g_off0[NDST0 + 1];
__device__ int g_cur0[NDST0];
__device__ int g_eidx0[NE0];
__device__ int g_cnt1[NDST1];
__device__ int g_off1[NDST1 + 1];
__device__ int g_cur1[NDST1];
__device__ int g_eidx1[NE1];

__device__ __align__(16) __nv_bfloat16 g_w1s_hi[H_F * IN_F];
__device__ __align__(16) __nv_bfloat16 g_w1s_lo[H_F * IN_F];
__device__ __align__(16) __nv_bfloat16 g_w1n_hi[H_F * IN_F];
__device__ __align__(16) __nv_bfloat16 g_w1n_lo[H_F * IN_F];
__device__ __align__(16) __nv_bfloat16 g_w2s_hi[N_CLS * H_F];
__device__ __align__(16) __nv_bfloat16 g_w2s_lo[N_CLS * H_F];
__device__ __align__(16) __nv_bfloat16 g_w2n_hi[N_CLS * H_F];
__device__ __align__(16) __nv_bfloat16 g_w2n_lo[N_CLS * H_F];

// ---------------------------------------------------------------------------
// helpers
// ---------------------------------------------------------------------------
__device__ __forceinline__ void cp16(uint32_t dst, const void* src, bool pred) {
    asm volatile("cp.async.cg.shared.global [%0], [%1], 16, %2;"
                 :: "r"(dst), "l"(src), "r"(pred ? 16 : 0));
}
__device__ __forceinline__ void split2(float x, float y,
                                       uint32_t& hi, uint32_t& lo) {
    __nv_bfloat16 hx = __float2bfloat16(x);
    __nv_bfloat16 hy = __float2bfloat16(y);
    __nv_bfloat16 lx = __float2bfloat16(x - __bfloat162float(hx));
    __nv_bfloat16 ly = __float2bfloat16(y - __bfloat162float(hy));
    hi = ((uint32_t)__bfloat16_as_ushort(hy) << 16) | __bfloat16_as_ushort(hx);
    lo = ((uint32_t)__bfloat16_as_ushort(ly) << 16) | __bfloat16_as_ushort(lx);
}
__device__ __forceinline__ void mma16816(float* c, const uint32_t* a,
                                         uint32_t b0, uint32_t b1) {
    asm volatile(
        "mma.sync.aligned.m16n8k16.row.col.f32.bf16.bf16.f32 "
        "{%0,%1,%2,%3}, {%4,%5,%6,%7}, {%8,%9}, {%0,%1,%2,%3};"
        : "+f"(c[0]), "+f"(c[1]), "+f"(c[2]), "+f"(c[3])
        : "r"(a[0]), "r"(a[1]), "r"(a[2]), "r"(a[3]), "r"(b0), "r"(b1));
}
#define LDSM4(r0, r1, r2, r3, addr) \
    asm volatile("ldmatrix.sync.aligned.m8n8.x4.shared.b16 {%0,%1,%2,%3}, [%4];" \
                 : "=r"(r0), "=r"(r1), "=r"(r2), "=r"(r3) : "r"(addr))

// ---------------------------------------------------------------------------
// CSR build
// ---------------------------------------------------------------------------
__global__ void zero_counts_kernel() {
    int i = blockIdx.x * blockDim.x + threadIdx.x;
    if (i < NDST0) g_cnt0[i] = 0;
    if (i < NDST1) g_cnt1[i] = 0;
}
__global__ void count_kernel(const int* __restrict__ edst, int* __restrict__ cnt, int E) {
    int e = blockIdx.x * blockDim.x + threadIdx.x;
    if (e < E) atomicAdd(&cnt[edst[e]], 1);
}
__global__ void __launch_bounds__(1024) scan_kernel() {
    const int n   = blockIdx.x == 0 ? NDST0 : NDST1;
    int* cnt = blockIdx.x == 0 ? g_cnt0 : g_cnt1;
    int* off = blockIdx.x == 0 ? g_off0 : g_off1;
    int* cur = blockIdx.x == 0 ? g_cur0 : g_cur1;
    __shared__ int part[1024];
    int tid = threadIdx.x;
    int chunk = (n + 1023) >> 10;
    int beg = tid * chunk, end = min(beg + chunk, n);
    int s = 0;
    for (int i = beg; i < end; i++) s += cnt[i];
    part[tid] = s;
    __syncthreads();
    for (int d = 1; d < 1024; d <<= 1) {
        int v = (tid >= d) ? part[tid - d] : 0;
        __syncthreads();
        part[tid] += v;
        __syncthreads();
    }
    int prefix = tid ? part[tid - 1] : 0;
    for (int i = beg; i < end; i++) {
        off[i] = prefix;
        cur[i] = prefix;
        prefix += cnt[i];
    }
    if (tid == 0) off[n] = part[1023];
}
__global__ void fill_kernel(const int* __restrict__ esrc, const int* __restrict__ edst,
                            int* __restrict__ cur, int* __restrict__ eidx, int E) {
    int e = blockIdx.x * blockDim.x + threadIdx.x;
    if (e >= E) return;
    int p = atomicAdd(&cur[edst[e]], 1);
    eidx[p] = esrc[e];
}

// ---------------------------------------------------------------------------
// Gather-mean + bf16 split
// ---------------------------------------------------------------------------
template <int F>
__global__ void __launch_bounds__(F / 4)
gather_mean_split(const float* __restrict__ feat,
                  const int* __restrict__ off, const int* __restrict__ eidx,
                  __nv_bfloat16* __restrict__ hi, __nv_bfloat16* __restrict__ lo) {
    int row = blockIdx.x;
    int tid = threadIdx.x;
    int beg = off[row], end = off[row + 1];
    float4 acc = make_float4(0.f, 0.f, 0.f, 0.f);
    int j = beg;
    for (; j + 2 <= end; j += 2) {
        int s0 = eidx[j], s1 = eidx[j + 1];
        float4 v0 = reinterpret_cast<const float4*>(feat)[(long long)s0 * (F / 4) + tid];
        float4 v1 = reinterpret_cast<const float4*>(feat)[(long long)s1 * (F / 4) + tid];
        acc.x += v0.x + v1.x; acc.y += v0.y + v1.y;
        acc.z += v0.z + v1.z; acc.w += v0.w + v1.w;
    }
    if (j < end) {
        float4 v = reinterpret_cast<const float4*>(feat)[(long long)eidx[j] * (F / 4) + tid];
        acc.x += v.x; acc.y += v.y; acc.z += v.z; acc.w += v.w;
    }
    float sc = 1.0f / (float)max(end - beg, 1);
    acc.x *= sc; acc.y *= sc; acc.z *= sc; acc.w *= sc;
    uint32_t h01, l01, h23, l23;
    split2(acc.x, acc.y, h01, l01);
    split2(acc.z, acc.w, h23, l23);
    long long o = (long long)row * (F / 4) + tid;
    reinterpret_cast<uint2*>(hi)[o] = make_uint2(h01, h23);
    reinterpret_cast<uint2*>(lo)[o] = make_uint2(l01, l23);
}

// ---------------------------------------------------------------------------
// Transpose + bf16 hi/lo split: W[K,N] -> hi/lo [N,K]
// ---------------------------------------------------------------------------
__global__ void transpose_split_kernel(const float* __restrict__ W,
                                       __nv_bfloat16* __restrict__ hi,
                                       __nv_bfloat16* __restrict__ lo,
                                       int K, int N) {
    __shared__ float t[32][33];
    int n0 = blockIdx.x * 32, k0 = blockIdx.y * 32;
    int tx = threadIdx.x, ty = threadIdx.y;
#pragma unroll
    for (int i = 0; i < 4; i++)
        t[ty + 8 * i][tx] = W[(long long)(k0 + ty + 8 * i) * N + n0 + tx];
    __syncthreads();
#pragma unroll
    for (int i = 0; i < 4; i++) {
        float v = t[tx][ty + 8 * i];
        __nv_bfloat16 h = __float2bfloat16(v);
        __nv_bfloat16 l = __float2bfloat16(v - __bfloat162float(h));
        long long o = (long long)(n0 + ty + 8 * i) * K + k0 + tx;
        hi[o] = h;
        lo[o] = l;
    }
}

__global__ void split_rows_kernel(const float* __restrict__ src,
                                  __nv_bfloat16* __restrict__ hi,
                                  __nv_bfloat16* __restrict__ lo,
                                  long long n4) {
    long long i = (long long)blockIdx.x * blockDim.x + threadIdx.x;
    if (i >= n4) return;
    float4 v = reinterpret_cast<const float4*>(src)[i];
    uint32_t h01, l01, h23, l23;
    split2(v.x, v.y, h01, l01);
    split2(v.z, v.w, h23, l23);
    reinterpret_cast<uint2*>(hi)[i] = make_uint2(h01, h23);
    reinterpret_cast<uint2*>(lo)[i] = make_uint2(l01, l23);
}

// ---------------------------------------------------------------------------
// Pipelined dual-pair split-bf16 GEMM with ldmatrix fragment loads:
//   C = act( A0 @ B0^T + A1 @ B1^T + bias ),  C += Ahi*Bhi + Ahi*Blo + Alo*Bhi
// ---------------------------------------------------------------------------
template <int NW_N>
__global__ void __launch_bounds__(256)
sage_mma_gemm(const __nv_bfloat16* __restrict__ A0hi, const __nv_bfloat16* __restrict__ A0lo,
              const __nv_bfloat16* __restrict__ A1hi, const __nv_bfloat16* __restrict__ A1lo,
              const __nv_bfloat16* __restrict__ B0hi, const __nv_bfloat16* __restrict__ B0lo,
              const __nv_bfloat16* __restrict__ B1hi, const __nv_bfloat16* __restrict__ B1lo,
              const float* __restrict__ bias, float* __restrict__ C,
              __nv_bfloat16* __restrict__ Chi, __nv_bfloat16* __restrict__ Clo,
              int splitRows, int M, int N, int K, int doRelu) {
    constexpr int BM = 32 * (8 / NW_N);      // 128 | 64
    constexpr int NJ = 128 / (8 * NW_N);     // 8 | 4
    constexpr int ATILE = BM * APAD;
    constexpr int BTILE = 128 * APAD;
    constexpr int SSTRIDE = 2 * ATILE + 2 * BTILE;

    extern __shared__ __nv_bfloat16 sm[];
    uint32_t sbase = (uint32_t)__cvta_generic_to_shared(sm);

    int tid = threadIdx.x;
    int wid = tid >> 5;
    int lane = tid & 31;
    int g = lane >> 2;
    int t = lane & 3;
    int warpM = wid / NW_N;
    int warpN = wid % NW_N;
    int rowC = blockIdx.y * BM;
    int colC = blockIdx.x * 128;

    // ldmatrix lane-offsets (bytes)
    const uint32_t offA = ((uint32_t)(((lane & 15) + warpM * 32) * APAD
                          + ((lane >> 4) << 3))) * 2;
    const uint32_t offBl = ((uint32_t)((((lane >> 4) << 3) + (lane & 7)) * APAD
                          + (((lane >> 3) & 1) << 3))) * 2;

    const int nk = K >> 5;
    const int total = 2 * nk;

    auto issue = [&](int q, int s) {
        int pass = q >= nk;
        int k0 = (pass ? q - nk : q) << 5;
        const __nv_bfloat16* Ah = pass ? A1hi : A0hi;
        const __nv_bfloat16* Al = pass ? A1lo : A0lo;
        const __nv_bfloat16* Bh = pass ? B1hi : B0hi;
        const __nv_bfloat16* Bl = pass ? B1lo : B0lo;
        uint32_t sb = sbase + (uint32_t)s * (SSTRIDE * 2);
#pragma unroll
        for (int it = 0; it < BM / 64; it++) {
            int u = tid + it * 256;
            int r = u >> 2, c = u & 3;
            int gr = rowC + r;
            bool p = gr < M;
            long long go = (long long)(p ? gr : 0) * K + k0 + (c << 3);
            uint32_t off = (uint32_t)(r * APAD + (c << 3)) * 2;
            cp16(sb + off, Ah + go, p);
            cp16(sb + ATILE * 2 + off, Al + go, p);
        }
#pragma unroll
        for (int it = 0; it < 2; it++) {
            int u = tid + it * 256;
            int r = u >> 2, c = u & 3;
            long long go = (long long)(colC + r) * K + k0 + (c << 3);
            uint32_t off = (uint32_t)(r * APAD + (c << 3)) * 2;
            cp16(sb + 2 * ATILE * 2 + off, Bh + go, true);
            cp16(sb + (2 * ATILE + BTILE) * 2 + off, Bl + go, true);
        }
        asm volatile("cp.async.commit_group;" ::: "memory");
    };

    float acc[2][NJ][4];
#pragma unroll
    for (int i = 0; i < 2; i++)
#pragma unroll
        for (int j = 0; j < NJ; j++)
#pragma unroll
            for (int q = 0; q < 4; q++) acc[i][j][q] = 0.0f;

    issue(0, 0);

#pragma unroll 1
    for (int q = 0; q < total; q++) {
        int s = q & 1;
        if (q + 1 < total) {
            issue(q + 1, s ^ 1);
            asm volatile("cp.async.wait_group 1;" ::: "memory");
        } else {
            asm volatile("cp.async.wait_group 0;" ::: "memory");
        }
        __syncthreads();

        uint32_t baseAhi = sbase + (uint32_t)s * (SSTRIDE * 2);
        uint32_t baseAlo = baseAhi + ATILE * 2;
        uint32_t baseBhi = baseAhi + 2 * ATILE * 2;
        uint32_t baseBlo = baseBhi + BTILE * 2;

#pragma unroll
        for (int ks = 0; ks < 2; ks++) {
            uint32_t kof = (uint32_t)ks * 32;   // 16 bf16 = 32 bytes
            // A-hi fragments (2 m16 tiles)
            uint32_t ah[2][4];
#pragma unroll
            for (int i = 0; i < 2; i++)
                LDSM4(ah[i][0], ah[i][1], ah[i][2], ah[i][3],
                      baseAhi + offA + (uint32_t)(i * 16 * APAD) * 2 + kof);
            // B-hi / B-lo fragments (NJ n8 tiles, loaded in n16 pairs)
            uint32_t bh[NJ][2], bl[NJ][2];
#pragma unroll
            for (int j2 = 0; j2 < NJ / 2; j2++) {
                uint32_t nbo = (uint32_t)((warpN * (NJ * 8) + j2 * 16) * APAD) * 2;
                LDSM4(bh[2 * j2][0], bh[2 * j2][1], bh[2 * j2 + 1][0], bh[2 * j2 + 1][1],
                      baseBhi + offBl + nbo + kof);
                LDSM4(bl[2 * j2][0], bl[2 * j2][1], bl[2 * j2 + 1][0], bl[2 * j2 + 1][1],
                      baseBlo + offBl + nbo + kof);
            }
            // term0: Ahi*Bhi, term1: Ahi*Blo
#pragma unroll
            for (int i = 0; i < 2; i++)
#pragma unroll
                for (int j = 0; j < NJ; j++) {
                    mma16816(acc[i][j], ah[i], bh[j][0], bh[j][1]);
                    mma16816(acc[i][j], ah[i], bl[j][0], bl[j][1]);
                }
            // term2: Alo*Bhi
            uint32_t al[2][4];
#pragma unroll
            for (int i = 0; i < 2; i++)
                LDSM4(al[i][0], al[i][1], al[i][2], al[i][3],
                      baseAlo + offA + (uint32_t)(i * 16 * APAD) * 2 + kof);
#pragma unroll
            for (int i = 0; i < 2; i++)
#pragma unroll
                for (int j = 0; j < NJ; j++)
                    mma16816(acc[i][j], al[i], bh[j][0], bh[j][1]);
        }
        __syncthreads();
    }

    // epilogue
#pragma unroll
    for (int i = 0; i < 2; i++) {
#pragma unroll
        for (int j = 0; j < NJ; j++) {
            int row = rowC + warpM * 32 + i * 16 + g;
            int col = colC + warpN * (NJ * 8) + j * 8 + 2 * t;
            float bx = bias[col], by = bias[col + 1];
            float2 v0, v1;
            v0.x = acc[i][j][0] + bx; v0.y = acc[i][j][1] + by;
            v1.x = acc[i][j][2] + bx; v1.y = acc[i][j][3] + by;
            if (doRelu) {
                v0.x = fmaxf(v0.x, 0.f); v0.y = fmaxf(v0.y, 0.f);
                v1.x = fmaxf(v1.x, 0.f); v1.y = fmaxf(v1.y, 0.f);
            }
            if (row < M)
                *reinterpret_cast<float2*>(C + (long long)row * N + col) = v0;
            if (row + 8 < M)
                *reinterpret_cast<float2*>(C + (long long)(row + 8) * N + col) = v1;
            if (Chi) {
                if (row < splitRows) {
                    uint32_t hh, ll;
                    split2(v0.x, v0.y, hh, ll);
                    *reinterpret_cast<uint32_t*>(Chi + (long long)row * N + col) = hh;
                    *reinterpret_cast<uint32_t*>(Clo + (long long)row * N + col) = ll;
                }
                if (row + 8 < splitRows) {
                    uint32_t hh, ll;
                    split2(v1.x, v1.y, hh, ll);
                    *reinterpret_cast<uint32_t*>(Chi + (long long)(row + 8) * N + col) = hh;
                    *reinterpret_cast<uint32_t*>(Clo + (long long)(row + 8) * N + col) = ll;
                }
            }
        }
    }
}

// ---------------------------------------------------------------------------
extern "C" void kernel_launch(void* const* d_in, const int* in_sizes, int n_in,
                              void* d_out, int out_size) {
    const float* x        = (const float*)d_in[0];
    const float* W_self1  = (const float*)d_in[1];
    const float* W_neigh1 = (const float*)d_in[2];
    const float* b1       = (const float*)d_in[3];
    const float* W_self2  = (const float*)d_in[4];
    const float* W_neigh2 = (const float*)d_in[5];
    const float* b2       = (const float*)d_in[6];
    const int*   e0_src   = (const int*)d_in[7];
    const int*   e0_dst   = (const int*)d_in[8];
    const int*   e1_src   = (const int*)d_in[9];
    const int*   e1_dst   = (const int*)d_in[10];
    float* out = (float*)d_out;

    float* h;
    cudaGetSymbolAddress((void**)&h, g_h);
    __nv_bfloat16 *xhi, *xlo, *a1hi, *a1lo, *hhi, *hlo, *a2hi, *a2lo;
    cudaGetSymbolAddress((void**)&xhi,  g_xhi);
    cudaGetSymbolAddress((void**)&xlo,  g_xlo);
    cudaGetSymbolAddress((void**)&a1hi, g_a1hi);
    cudaGetSymbolAddress((void**)&a1lo, g_a1lo);
    cudaGetSymbolAddress((void**)&hhi,  g_hhi);
    cudaGetSymbolAddress((void**)&hlo,  g_hlo);
    cudaGetSymbolAddress((void**)&a2hi, g_a2hi);
    cudaGetSymbolAddress((void**)&a2lo, g_a2lo);
    __nv_bfloat16 *w1s_hi, *w1s_lo, *w1n_hi, *w1n_lo, *w2s_hi, *w2s_lo, *w2n_hi, *w2n_lo;
    cudaGetSymbolAddress((void**)&w1s_hi, g_w1s_hi);
    cudaGetSymbolAddress((void**)&w1s_lo, g_w1s_lo);
    cudaGetSymbolAddress((void**)&w1n_hi, g_w1n_hi);
    cudaGetSymbolAddress((void**)&w1n_lo, g_w1n_lo);
    cudaGetSymbolAddress((void**)&w2s_hi, g_w2s_hi);
    cudaGetSymbolAddress((void**)&w2s_lo, g_w2s_lo);
    cudaGetSymbolAddress((void**)&w2n_hi, g_w2n_hi);
    cudaGetSymbolAddress((void**)&w2n_lo, g_w2n_lo);
    int *cnt0, *off0, *cur0, *eidx0, *cnt1, *off1, *cur1, *eidx1;
    cudaGetSymbolAddress((void**)&cnt0, g_cnt0);
    cudaGetSymbolAddress((void**)&off0, g_off0);
    cudaGetSymbolAddress((void**)&cur0, g_cur0);
    cudaGetSymbolAddress((void**)&eidx0, g_eidx0);
    cudaGetSymbolAddress((void**)&cnt1, g_cnt1);
    cudaGetSymbolAddress((void**)&off1, g_off1);
    cudaGetSymbolAddress((void**)&cur1, g_cur1);
    cudaGetSymbolAddress((void**)&eidx1, g_eidx1);

    constexpr int SMEM1 = (2 * (2 * 128 * APAD + 2 * 128 * APAD)) * 2;
    constexpr int SMEM2 = (2 * (2 * 64 * APAD + 2 * 128 * APAD)) * 2;
    static bool attr_set = false;
    if (!attr_set) {
        cudaFuncSetAttribute(sage_mma_gemm<2>, cudaFuncAttributeMaxDynamicSharedMemorySize, SMEM1);
        cudaFuncSetAttribute(sage_mma_gemm<4>, cudaFuncAttributeMaxDynamicSharedMemorySize, SMEM2);
        attr_set = true;
    }

    // 1. CSR build
    zero_counts_kernel<<<(NDST0 + 255) / 256, 256>>>();
    count_kernel<<<(NE0 + 255) / 256, 256>>>(e0_dst, cnt0, NE0);
    count_kernel<<<(NE1 + 255) / 256, 256>>>(e1_dst, cnt1, NE1);
    scan_kernel<<<2, 1024>>>();
    fill_kernel<<<(NE0 + 255) / 256, 256>>>(e0_src, e0_dst, cur0, eidx0, NE0);
    fill_kernel<<<(NE1 + 255) / 256, 256>>>(e1_src, e1_dst, cur1, eidx1, NE1);

    // 2. weight transpose + split; x split
    {
        dim3 b(32, 8);
        transpose_split_kernel<<<dim3(H_F / 32, IN_F / 32), b>>>(W_self1,  w1s_hi, w1s_lo, IN_F, H_F);
        transpose_split_kernel<<<dim3(H_F / 32, IN_F / 32), b>>>(W_neigh1, w1n_hi, w1n_lo, IN_F, H_F);
        transpose_split_kernel<<<dim3(N_CLS / 32, H_F / 32), b>>>(W_self2,  w2s_hi, w2s_lo, H_F, N_CLS);
        transpose_split_kernel<<<dim3(N_CLS / 32, H_F / 32), b>>>(W_neigh2, w2n_hi, w2n_lo, H_F, N_CLS);
        long long n4 = (long long)NDST0 * IN_F / 4;
        split_rows_kernel<<<(int)((n4 + 255) / 256), 256>>>(x, xhi, xlo, n4);
    }
    // 3. layer-1 gather-mean
    gather_mean_split<IN_F><<<NDST0, IN_F / 4>>>(x, off0, eidx0, a1hi, a1lo);

    // 4. layer-1 dual-GEMM + bias + ReLU -> h (+ split of h[:NDST1])
    {
        dim3 grid(H_F / 128, (NDST0 + 127) / 128);
        sage_mma_gemm<2><<<grid, 256, SMEM1>>>(
            xhi, xlo, a1hi, a1lo, w1s_hi, w1s_lo, w1n_hi, w1n_lo,
            b1, h, hhi, hlo, NDST1, NDST0, H_F, IN_F, 1);
    }
    // 5. layer-2 gather-mean
    gather_mean_split<H_F><<<NDST1, H_F / 4>>>(h, off1, eidx1, a2hi, a2lo);

    // 6. layer-2 dual-GEMM + bias -> out
    {
        dim3 grid(N_CLS / 128, (NDST1 + 63) / 64);
        sage_mma_gemm<4><<<grid, 256, SMEM2>>>(
            hhi, hlo, a2hi, a2lo, w2s_hi, w2s_lo, w2n_hi, w2n_lo,
            b2, out, nullptr, nullptr, 0, NDST1, N_CLS, H_F, 0);
    }
}